// round 6
// baseline (speedup 1.0000x reference)
#include <cuda_runtime.h>
#include <cuda_bf16.h>
#include <cstdint>
#include <math.h>

// ---------------- problem constants ----------------
constexpr int kN    = 8192;
constexpr int kC0   = 64;
constexpr int kC1   = 32;
constexpr int kP0   = kC0*(kC0+1)/2;      // 2080
constexpr int kP1   = kC1*(kC1+1)/2;      // 528
constexpr int kA1   = kC1*(kC1-1)/2;      // 496
constexpr int kM0   = kC0 + kP0 + kP1;    // 2672
constexpr int kM1   = kC1 + kC0*kC1;      // 2080
constexpr int kG    = kM0 + kM1 + kA1 + kP1; // 5776
constexpr int kOUTW = 64 + 32*3 + 16*3 + 16*5; // 288

// ---------------- scratch (static device globals; no allocation) ----------------
__device__ float d_f0 [(size_t)kN*kM0];
__device__ float d_h  [(size_t)kN*kM0];
__device__ float d_g  [(size_t)kN*kG];
__device__ float d_f1 [3][(size_t)kN*kM1];
__device__ float d_f1e[3][(size_t)kN*kA1];
__device__ float d_f2 [5][(size_t)kN*kP1];
// int8 hi/lo split operands + scales
__device__ int8_t d_f0qh[(size_t)kN*kM0];
__device__ int8_t d_f0ql[(size_t)kN*kM0];
__device__ int8_t d_hqh [(size_t)kN*kM0];
__device__ int8_t d_hql [(size_t)kN*kM0];
__device__ int8_t d_w1qh[(size_t)kM0*kM0];   // [N=2672][K=2672] K-major
__device__ int8_t d_w1ql[(size_t)kM0*kM0];
__device__ int8_t d_w2qh[(size_t)kG*kM0];    // [N=5776][K=2672] K-major
__device__ int8_t d_w2ql[(size_t)kG*kM0];
__device__ float d_sA0[kN];
__device__ float d_sAh[kN];
__device__ float d_sB1[kM0];
__device__ float d_sB2[kG];

// ---------------- PTX helpers ----------------
__device__ __forceinline__ uint32_t smem_u32(const void* p) {
    uint32_t a;
    asm("{ .reg .u64 t; cvta.to.shared.u64 t, %1; cvt.u32.u64 %0, t; }" : "=r"(a) : "l"(p));
    return a;
}
__device__ __forceinline__ void cp16(uint32_t dst, const void* src, bool pred) {
    int sz = pred ? 16 : 0;
    asm volatile("cp.async.cg.shared.global [%0], [%1], 16, %2;"
                 :: "r"(dst), "l"(src), "r"(sz) : "memory");
}
__device__ __forceinline__ void cp_commit() {
    asm volatile("cp.async.commit_group;" ::: "memory");
}
template<int NG>
__device__ __forceinline__ void cp_wait() {
    asm volatile("cp.async.wait_group %0;" :: "n"(NG) : "memory");
}
__device__ __forceinline__ void ldm_x4(uint32_t* r, uint32_t addr) {
    asm volatile("ldmatrix.sync.aligned.m8n8.x4.shared.b16 {%0,%1,%2,%3}, [%4];"
                 : "=r"(r[0]), "=r"(r[1]), "=r"(r[2]), "=r"(r[3]) : "r"(addr));
}
__device__ __forceinline__ void mma_s8(int* c, const uint32_t* a, const uint32_t* b) {
    asm volatile("mma.sync.aligned.m16n8k32.row.col.s32.s8.s8.s32 "
                 "{%0,%1,%2,%3}, {%4,%5,%6,%7}, {%8,%9}, {%0,%1,%2,%3};"
                 : "+r"(c[0]), "+r"(c[1]), "+r"(c[2]), "+r"(c[3])
                 : "r"(a[0]), "r"(a[1]), "r"(a[2]), "r"(a[3]), "r"(b[0]), "r"(b[1]));
}

// x = s*(qh + ql/252), s = rowmax/127, invs = 1/s
__device__ __forceinline__ void quant_pair(float x, float invs, int8_t& qh, int8_t& ql)
{
    float q   = x * invs;
    int   qhi = __float2int_rn(q);
    float r   = q - (float)qhi;
    int   qlo = __float2int_rn(r * 252.0f);
    qh = (int8_t)qhi; ql = (int8_t)qlo;
}

// ---------------- triu decode ----------------
__device__ __forceinline__ int2 triu_decode(int p, int C, int k)
{
    int Cm = C - k;
    float t = 2.0f*Cm + 1.0f;
    int a = (int)((t - sqrtf(t*t - 8.0f*(float)p)) * 0.5f);
    if (a < 0) a = 0;
    if (a > Cm-1) a = Cm-1;
    while (a > 0 && a*Cm - (a*(a-1))/2 > p) --a;
    while ((a+1)*Cm - ((a+1)*a)/2 <= p) ++a;
    int b = a + k + (p - (a*Cm - (a*(a-1))/2));
    return make_int2(a, b);
}

// ---------------- stage 0a: per-output-column absmax of W [K x N] ----------------
__global__ __launch_bounds__(256)
void colmax_kernel(const float* __restrict__ W, float* __restrict__ sB, int K, int N)
{
    __shared__ float red[8][32];
    int tx = threadIdx.x & 31, ty = threadIdx.x >> 5;
    int c  = blockIdx.x*32 + tx;
    float m = 0.f;
    if (c < N)
        for (int k = ty; k < K; k += 8)
            m = fmaxf(m, fabsf(W[(size_t)k*N + c]));
    red[ty][tx] = m;
    __syncthreads();
    if (ty == 0) {
        #pragma unroll
        for (int j = 1; j < 8; j++) m = fmaxf(m, red[j][tx]);
        if (c < N) sB[c] = m * (1.0f/127.0f);
    }
}

// ---------------- stage 0b: transpose + int8 hi/lo quantize ----------------
__global__ __launch_bounds__(256)
void quant_weight(const float* __restrict__ W, const float* __restrict__ sB,
                  int8_t* __restrict__ Qhi, int8_t* __restrict__ Qlo, int K, int N)
{
    __shared__ float tile[32][33];
    int kb = blockIdx.y*32, nb = blockIdx.x*32;
    int tx = threadIdx.x & 31, ty = threadIdx.x >> 5;
    for (int i = ty; i < 32; i += 8) {
        int k = kb + i, n = nb + tx;
        tile[i][tx] = (k < K && n < N) ? W[(size_t)k*N + n] : 0.f;
    }
    __syncthreads();
    for (int i = ty; i < 32; i += 8) {
        int n = nb + i, k = kb + tx;
        if (n < N && k < K) {
            float s = sB[n];
            float invs = (s > 0.f) ? 1.0f/s : 0.f;
            int8_t qh, ql;
            quant_pair(tile[tx][i], invs, qh, ql);
            Qhi[(size_t)n*K + k] = qh;
            Qlo[(size_t)n*K + k] = ql;
        }
    }
}

// ---------------- stage 1: feature construction + f0 quantization ----------------
__global__ __launch_bounds__(256)
void build_features(const float* __restrict__ xs, const float* __restrict__ xv)
{
    const int n = blockIdx.x;
    __shared__ float s[kC0];
    __shared__ float v[kC1][3];
    __shared__ float f0row[kM0];
    __shared__ float wmax[8];
    const int t = threadIdx.x;
    const int wid = t >> 5, lane = t & 31;
    if (t < kC0) s[t] = xs[(size_t)n*kC0 + t];
    if (t >= 128 && t < 128 + kC1*3) ((float*)v)[t-128] = xv[(size_t)n*kC1*3 + (t-128)];
    __syncthreads();

    const float RS2 = 0.70710678118654752f;
    const float RS3 = 0.57735026918962576f;
    const float S6  = 0.40824829046386302f;

    float lmax = 0.f;
    if (t < kC0) { float x = s[t]; f0row[t] = x; lmax = fmaxf(lmax, fabsf(x)); }
    for (int p = t; p < kP0; p += 256) {
        int2 ab = triu_decode(p, kC0, 0);
        float c = (ab.x == ab.y) ? RS2 : 1.0f;
        float x = s[ab.x]*s[ab.y]*c;
        f0row[kC0 + p] = x; lmax = fmaxf(lmax, fabsf(x));
    }
    for (int p = t; p < kP1; p += 256) {
        int2 ab = triu_decode(p, kC1, 0);
        float c = ((ab.x == ab.y) ? RS2 : 1.0f) * RS3;
        float x = (v[ab.x][0]*v[ab.y][0] + v[ab.x][1]*v[ab.y][1] + v[ab.x][2]*v[ab.y][2]) * c;
        f0row[kC0 + kP0 + p] = x; lmax = fmaxf(lmax, fabsf(x));
    }
    // warp + block max reduce
    #pragma unroll
    for (int o = 16; o > 0; o >>= 1)
        lmax = fmaxf(lmax, __shfl_xor_sync(0xFFFFFFFF, lmax, o));
    if (lane == 0) wmax[wid] = lmax;
    __syncthreads();
    if (t == 0) {
        float m = wmax[0];
        #pragma unroll
        for (int j = 1; j < 8; j++) m = fmaxf(m, wmax[j]);
        d_sA0[n] = m * (1.0f/127.0f);
        wmax[0] = m;
    }
    __syncthreads();
    {
        float m = wmax[0];
        float invs = (m > 0.f) ? 127.0f/m : 0.f;
        float* f0 = d_f0 + (size_t)n*kM0;
        int8_t* qh = d_f0qh + (size_t)n*kM0;
        int8_t* ql = d_f0ql + (size_t)n*kM0;
        for (int i = t; i < kM0; i += 256) {
            float x = f0row[i];
            f0[i] = x;
            quant_pair(x, invs, qh[i], ql[i]);
        }
    }
    // f1 / f1e / f2 (unchanged)
    for (int c = t; c < kM1; c += 256) {
        float e0, e1, e2;
        if (c < kC1) { e0 = v[c][0]; e1 = v[c][1]; e2 = v[c][2]; }
        else {
            int cc = (c - kC1) >> 5;
            int vv = (c - kC1) & 31;
            float sc = s[cc];
            e0 = sc*v[vv][0]; e1 = sc*v[vv][1]; e2 = sc*v[vv][2];
        }
        size_t idx = (size_t)n*kM1 + c;
        d_f1[0][idx] = e0; d_f1[1][idx] = e1; d_f1[2][idx] = e2;
    }
    for (int p = t; p < kA1; p += 256) {
        int2 ab = triu_decode(p, kC1, 1);
        float ux = v[ab.x][0], uy = v[ab.x][1], uz = v[ab.x][2];
        float wx = v[ab.y][0], wy = v[ab.y][1], wz = v[ab.y][2];
        size_t idx = (size_t)n*kA1 + p;
        d_f1e[0][idx] = (uy*wz - uz*wy) * RS2;
        d_f1e[1][idx] = (uz*wx - ux*wz) * RS2;
        d_f1e[2][idx] = (ux*wy - uy*wx) * RS2;
    }
    for (int p = t; p < kP1; p += 256) {
        int2 ab = triu_decode(p, kC1, 0);
        float c = (ab.x == ab.y) ? RS2 : 1.0f;
        float ax = v[ab.x][0], ay = v[ab.x][1], az = v[ab.x][2];
        float bx = v[ab.y][0], by = v[ab.y][1], bz = v[ab.y][2];
        size_t idx = (size_t)n*kP1 + p;
        d_f2[0][idx] = RS2*(ax*by + ay*bx)*c;
        d_f2[1][idx] = RS2*(ay*bz + az*by)*c;
        d_f2[2][idx] = RS2*(ax*bz + az*bx)*c;
        d_f2[3][idx] = RS2*(ax*bx - ay*by)*c;
        d_f2[4][idx] = S6*(-ax*bx - ay*by + 2.0f*az*bz)*c;
    }
}

// ---------------- stage 2b: quantize h rows ----------------
__global__ __launch_bounds__(256)
void quant_h()
{
    const int n = blockIdx.x;
    __shared__ float row[kM0];
    __shared__ float wmax[8];
    const int t = threadIdx.x;
    const int wid = t >> 5, lane = t & 31;
    const float* h = d_h + (size_t)n*kM0;
    float lmax = 0.f;
    for (int i = t; i < kM0; i += 256) {
        float x = h[i];
        row[i] = x;
        lmax = fmaxf(lmax, fabsf(x));
    }
    #pragma unroll
    for (int o = 16; o > 0; o >>= 1)
        lmax = fmaxf(lmax, __shfl_xor_sync(0xFFFFFFFF, lmax, o));
    if (lane == 0) wmax[wid] = lmax;
    __syncthreads();
    if (t == 0) {
        float m = wmax[0];
        #pragma unroll
        for (int j = 1; j < 8; j++) m = fmaxf(m, wmax[j]);
        d_sAh[n] = m * (1.0f/127.0f);
        wmax[0] = m;
    }
    __syncthreads();
    float m = wmax[0];
    float invs = (m > 0.f) ? 127.0f/m : 0.f;
    int8_t* qh = d_hqh + (size_t)n*kM0;
    int8_t* ql = d_hql + (size_t)n*kM0;
    for (int i = t; i < kM0; i += 256)
        quant_pair(row[i], invs, qh[i], ql[i]);
}

// ---- int8x3 IMMA GEMM: 128x128 tile, 512 thr (16 warps, warp 32x32), BK=64, 3 stages ----
constexpr int kRowStride  = 80;                     // 64B data + 16B pad
constexpr int kTileBytes  = 128 * kRowStride;       // 10240
constexpr int kBufBytes   = 4 * kTileBytes;         // Ah, Al, Bh, Bl = 40960
constexpr int kStages     = 3;
constexpr int kGemmSmem   = kStages * kBufBytes;    // 122880

template<bool SILU>
__global__ __launch_bounds__(512, 1)
void imma_gemm(const int8_t* __restrict__ Ahi, const int8_t* __restrict__ Alo,
               const int8_t* __restrict__ Bhi, const int8_t* __restrict__ Blo,
               const float* __restrict__ sA, const float* __restrict__ sB,
               float* __restrict__ Cout, int K, int Nglob)
{
    extern __shared__ char smem[];
    const uint32_t sbase = smem_u32(smem);
    const int tid  = threadIdx.x;
    const int wid  = tid >> 5, lane = tid & 31;
    const int m0   = blockIdx.y * 128;
    const int n0   = blockIdx.x * 128;
    const int wm   = (wid & 3)  * 32;     // 4 M-warps
    const int wn   = (wid >> 2) * 32;     // 4 N-warps

    int acc1[2][4][4], acc2[2][4][4];
    #pragma unroll
    for (int i = 0; i < 2; i++)
        #pragma unroll
        for (int j = 0; j < 4; j++)
            #pragma unroll
            for (int q = 0; q < 4; q++) { acc1[i][j][q] = 0; acc2[i][j][q] = 0; }

    const int nChunks = (K + 63) / 64;    // 42

    // ---- loader: 2048 x 16B per chunk (Ah 512 | Al 512 | Bh 512 | Bl 512) ----
    auto load_chunk = [&](int c) {
        const uint32_t db = sbase + (uint32_t)(c % kStages) * kBufBytes;
        const int k0 = c * 64;
        #pragma unroll
        for (int t = 0; t < 4; t++) {
            int idx  = t * 512 + tid;           // 0..2047
            int tile = idx >> 9;                // 0..3
            int rem  = idx & 511;
            int row  = rem >> 2;
            int kc   = rem & 3;
            int gk   = k0 + kc * 16;            // 16 int8 per uint4
            bool kok = gk < K;                  // K % 16 == 0
            uint32_t dst = db + (uint32_t)tile * kTileBytes
                         + (uint32_t)row * kRowStride + kc * 16;
            const int8_t* src;
            bool ok;
            if (tile < 2) {
                const int8_t* base = (tile == 0) ? Ahi : Alo;
                src = base + (size_t)(m0 + row) * K + (kok ? gk : 0);
                ok  = kok;
            } else {
                const int8_t* base = (tile == 2) ? Bhi : Blo;
                int gn = n0 + row;
                bool nok = gn < Nglob;
                src = base + (size_t)(nok ? gn : 0) * K + (kok ? gk : 0);
                ok  = kok && nok;
            }
            cp16(dst, src, ok);
        }
        cp_commit();
    };

    load_chunk(0);
    load_chunk(1);

    for (int c = 0; c < nChunks; c++) {
        if (c + 1 < nChunks) cp_wait<1>(); else cp_wait<0>();
        __syncthreads();
        if (c + 2 < nChunks) load_chunk(c + 2);

        const uint32_t db = sbase + (uint32_t)(c % kStages) * kBufBytes;
        const uint32_t aH = db, aL = db + kTileBytes;
        const uint32_t bH = db + 2*kTileBytes, bL = db + 3*kTileBytes;

        #pragma unroll
        for (int ks = 0; ks < 2; ks++) {       // two k32 halves of the 64B row
            uint32_t ah[2][4], al[2][4], bh[4][2], bl[4][2];
            const int arow = wm + (lane & 15);
            const int acol = ks * 32 + (lane >> 4) * 16;   // bytes
            #pragma unroll
            for (int mt = 0; mt < 2; mt++) {
                uint32_t off = (uint32_t)(arow + mt*16) * kRowStride + acol;
                ldm_x4(ah[mt], aH + off);
                ldm_x4(al[mt], aL + off);
            }
            // B: one x4 covers two n-tiles (both k-halves), lane-programmed
            const int bg  = lane >> 3;
            const int br  = lane & 7;
            const int bnt = bg >> 1;
            const int bkh = (bg & 1) * 16;
            #pragma unroll
            for (int np = 0; np < 2; np++) {
                uint32_t off = (uint32_t)(wn + (np*2 + bnt)*8 + br) * kRowStride
                             + ks*32 + bkh;
                ldm_x4(&bh[np*2][0], bH + off);
                ldm_x4(&bl[np*2][0], bL + off);
            }
            #pragma unroll
            for (int mt = 0; mt < 2; mt++)
                #pragma unroll
                for (int nt = 0; nt < 4; nt++) {
                    mma_s8(acc1[mt][nt], ah[mt], bh[nt]);
                    mma_s8(acc2[mt][nt], ah[mt], bl[nt]);
                    mma_s8(acc2[mt][nt], al[mt], bh[nt]);
                }
        }
    }

    // ---- epilogue: dequant v = sA[r]*sB[c]*(acc1 + acc2/252) ----
    const float kInv252 = 1.0f / 252.0f;
    #pragma unroll
    for (int mt = 0; mt < 2; mt++) {
        #pragma unroll
        for (int nt = 0; nt < 4; nt++) {
            int row = m0 + wm + mt*16 + (lane >> 2);
            int col = n0 + wn + nt*8 + (lane & 3) * 2;
            if (col < Nglob) {
                float sb0 = sB[col], sb1 = sB[col+1];
                #pragma unroll
                for (int half = 0; half < 2; half++) {
                    int r = row + half * 8;
                    float sa = sA[r];
                    float v0 = sa*sb0*((float)acc1[mt][nt][half*2+0]
                                       + (float)acc2[mt][nt][half*2+0]*kInv252);
                    float v1 = sa*sb1*((float)acc1[mt][nt][half*2+1]
                                       + (float)acc2[mt][nt][half*2+1]*kInv252);
                    if (SILU) {
                        v0 = v0 / (1.0f + __expf(-v0));
                        v1 = v1 / (1.0f + __expf(-v1));
                    }
                    size_t o = (size_t)r * Nglob + col;
                    Cout[o]   = v0;
                    Cout[o+1] = v1;
                }
            }
        }
    }
}

// ---------------- stage 5: skinny output GEMMs with fused gating ----------------
template<int OC>
__global__ __launch_bounds__(256)
void skinny_gemm(const float* __restrict__ A, const float* __restrict__ gAll, int gOff,
                 const float* __restrict__ W, float* __restrict__ out,
                 int K, int outBase, int outStride)
{
    constexpr int BR = 32, BK = 32;
    constexpr int G   = 256 / OC;
    constexpr int RPT = BR / G;
    __shared__ float As[BR][BK + 1];
    __shared__ float Ws[BK][OC];
    const int tid  = threadIdx.x;
    const int row0 = blockIdx.x * BR;
    const int col  = tid % OC;
    const int rg   = tid / OC;

    float acc[RPT];
    #pragma unroll
    for (int r = 0; r < RPT; r++) acc[r] = 0.0f;

    for (int k0 = 0; k0 < K; k0 += BK) {
        int r  = tid >> 3;
        int kc = (tid & 7) << 2;
        float4 a4 = make_float4(0.f, 0.f, 0.f, 0.f);
        if (k0 + kc + 4 <= K) {
            a4 = *reinterpret_cast<const float4*>(A + (size_t)(row0 + r)*K + k0 + kc);
            float4 g4 = *reinterpret_cast<const float4*>(
                gAll + (size_t)(row0 + r)*kG + gOff + k0 + kc);
            a4.x *= g4.x; a4.y *= g4.y; a4.z *= g4.z; a4.w *= g4.w;
        }
        As[r][kc] = a4.x; As[r][kc+1] = a4.y; As[r][kc+2] = a4.z; As[r][kc+3] = a4.w;
        for (int idx = tid; idx < BK*OC; idx += 256) {
            int kk = idx / OC, oo = idx % OC;
            Ws[kk][oo] = (k0 + kk < K) ? W[(size_t)(k0 + kk)*OC + oo] : 0.0f;
        }
        __syncthreads();
        #pragma unroll
        for (int kk = 0; kk < BK; kk++) {
            float wv = Ws[kk][col];
            #pragma unroll
            for (int rr = 0; rr < RPT; rr++)
                acc[rr] = fmaf(As[rg + rr*G][kk], wv, acc[rr]);
        }
        __syncthreads();
    }
    #pragma unroll
    for (int rr = 0; rr < RPT; rr++)
        out[(size_t)(row0 + rg + rr*G)*kOUTW + outBase + col*outStride] = acc[rr];
}

// ---------------- launch ----------------
extern "C" void kernel_launch(void* const* d_in, const int* in_sizes, int n_in,
                              void* d_out, int out_size)
{
    const float* xs  = (const float*)d_in[0];
    const float* xv  = (const float*)d_in[1];
    const float* w1  = (const float*)d_in[2];
    const float* w2  = (const float*)d_in[3];
    const float* w0  = (const float*)d_in[4];
    const float* w1o = (const float*)d_in[5];
    const float* w1e = (const float*)d_in[6];
    const float* w2e = (const float*)d_in[7];
    float* out = (float*)d_out;

    void *pf0, *ph, *pg, *pf1, *pf1e, *pf2;
    void *pf0qh, *pf0ql, *phqh, *phql, *pw1h, *pw1l, *pw2h, *pw2l;
    void *psA0, *psAh, *psB1, *psB2;
    cudaGetSymbolAddress(&pf0,  d_f0);
    cudaGetSymbolAddress(&ph,   d_h);
    cudaGetSymbolAddress(&pg,   d_g);
    cudaGetSymbolAddress(&pf1,  d_f1);
    cudaGetSymbolAddress(&pf1e, d_f1e);
    cudaGetSymbolAddress(&pf2,  d_f2);
    cudaGetSymbolAddress(&pf0qh, d_f0qh);
    cudaGetSymbolAddress(&pf0ql, d_f0ql);
    cudaGetSymbolAddress(&phqh,  d_hqh);
    cudaGetSymbolAddress(&phql,  d_hql);
    cudaGetSymbolAddress(&pw1h,  d_w1qh);
    cudaGetSymbolAddress(&pw1l,  d_w1ql);
    cudaGetSymbolAddress(&pw2h,  d_w2qh);
    cudaGetSymbolAddress(&pw2l,  d_w2ql);
    cudaGetSymbolAddress(&psA0,  d_sA0);
    cudaGetSymbolAddress(&psAh,  d_sAh);
    cudaGetSymbolAddress(&psB1,  d_sB1);
    cudaGetSymbolAddress(&psB2,  d_sB2);

    float* f0v  = (float*)pf0;
    float* hv   = (float*)ph;
    float* gv   = (float*)pg;
    float* f1v  = (float*)pf1;
    float* f1ev = (float*)pf1e;
    float* f2v  = (float*)pf2;
    int8_t* f0qh = (int8_t*)pf0qh;
    int8_t* f0ql = (int8_t*)pf0ql;
    int8_t* hqh  = (int8_t*)phqh;
    int8_t* hql  = (int8_t*)phql;
    int8_t* w1qh = (int8_t*)pw1h;
    int8_t* w1ql = (int8_t*)pw1l;
    int8_t* w2qh = (int8_t*)pw2h;
    int8_t* w2ql = (int8_t*)pw2l;
    float* sA0 = (float*)psA0;
    float* sAh = (float*)psAh;
    float* sB1 = (float*)psB1;
    float* sB2 = (float*)psB2;

    cudaFuncSetAttribute(imma_gemm<true>,  cudaFuncAttributeMaxDynamicSharedMemorySize, kGemmSmem);
    cudaFuncSetAttribute(imma_gemm<false>, cudaFuncAttributeMaxDynamicSharedMemorySize, kGemmSmem);

    // stage 0: weight column scales + transpose-quantize
    colmax_kernel<<<(kM0+31)/32, 256>>>(w1, sB1, kM0, kM0);
    colmax_kernel<<<(kG +31)/32, 256>>>(w2, sB2, kM0, kG);
    quant_weight<<<dim3((kM0+31)/32, (kM0+31)/32), 256>>>(w1, sB1, w1qh, w1ql, kM0, kM0);
    quant_weight<<<dim3((kG +31)/32, (kM0+31)/32), 256>>>(w2, sB2, w2qh, w2ql, kM0, kG);

    // stage 1: features (+ f0 quantization)
    build_features<<<kN, 256>>>(xs, xv);

    // stage 2: h = silu(f0 @ W1) fp32        [8192 x 2672]
    {
        dim3 grid((kM0 + 127)/128, kN/128);
        imma_gemm<true><<<grid, 512, kGemmSmem>>>(f0qh, f0ql, w1qh, w1ql,
                                                  sA0, sB1, hv, kM0, kM0);
    }
    // stage 2b: quantize h rows
    quant_h<<<kN, 256>>>();

    // stage 3: g = h @ W2 fp32               [8192 x 5776]
    {
        dim3 grid((kG + 127)/128, kN/128);
        imma_gemm<false><<<grid, 512, kGemmSmem>>>(hqh, hql, w2qh, w2ql,
                                                   sAh, sB2, gv, kM0, kG);
    }

    // stage 5: gated outputs into [N,288] (gate fused into A-load)
    skinny_gemm<64><<<kN/32, 256>>>(f0v, gv, 0, w0, out, kM0, 0, 1);
    for (int i = 0; i < 3; i++)
        skinny_gemm<32><<<kN/32, 256>>>(f1v + (size_t)i*kN*kM1, gv, kM0,
                                        w1o, out, kM1, 64 + i, 3);
    for (int i = 0; i < 3; i++)
        skinny_gemm<16><<<kN/32, 256>>>(f1ev + (size_t)i*kN*kA1, gv, kM0 + kM1,
                                        w1e, out, kA1, 160 + i, 3);
    for (int m = 0; m < 5; m++)
        skinny_gemm<16><<<kN/32, 256>>>(f2v + (size_t)m*kN*kP1, gv, kM0 + kM1 + kA1,
                                        w2e, out, kP1, 208 + m, 5);
}

// round 7
// speedup vs baseline: 2.5270x; 2.5270x over previous
#include <cuda_runtime.h>
#include <cuda_bf16.h>
#include <cstdint>
#include <math.h>

// ---------------- problem constants ----------------
constexpr int kN    = 8192;
constexpr int kC0   = 64;
constexpr int kC1   = 32;
constexpr int kP0   = kC0*(kC0+1)/2;      // 2080
constexpr int kP1   = kC1*(kC1+1)/2;      // 528
constexpr int kA1   = kC1*(kC1-1)/2;      // 496
constexpr int kM0   = kC0 + kP0 + kP1;    // 2672
constexpr int kM1   = kC1 + kC0*kC1;      // 2080
constexpr int kG    = kM0 + kM1 + kA1 + kP1; // 5776
constexpr int kOUTW = 64 + 32*3 + 16*3 + 16*5; // 288

// ---------------- scratch (static device globals; no allocation) ----------------
__device__ float d_f0 [(size_t)kN*kM0];   // exact fp32 (skinny path)
__device__ float d_f0t[(size_t)kN*kM0];   // tf32-rounded (GEMM A)
__device__ float d_h  [(size_t)kN*kM0];   // tf32-rounded silu output
__device__ float d_g  [(size_t)kN*kG];
__device__ float d_f1 [3][(size_t)kN*kM1];
__device__ float d_f1e[3][(size_t)kN*kA1];
__device__ float d_f2 [5][(size_t)kN*kP1];
__device__ float d_w1t[(size_t)kM0*kM0];  // [N=2672][K=2672] K-major, tf32-rounded
__device__ float d_w2t[(size_t)kG*kM0];   // [N=5776][K=2672] K-major, tf32-rounded

// ---------------- PTX helpers (family-portable: sm_80+ mma.sync / cp.async) ----------------
__device__ __forceinline__ uint32_t smem_u32(const void* p) {
    uint32_t a;
    asm("{ .reg .u64 t; cvta.to.shared.u64 t, %1; cvt.u32.u64 %0, t; }" : "=r"(a) : "l"(p));
    return a;
}
__device__ __forceinline__ void cp16(uint32_t dst, const void* src, bool pred) {
    int sz = pred ? 16 : 0;
    asm volatile("cp.async.cg.shared.global [%0], [%1], 16, %2;"
                 :: "r"(dst), "l"(src), "r"(sz) : "memory");
}
__device__ __forceinline__ void cp_commit() {
    asm volatile("cp.async.commit_group;" ::: "memory");
}
template<int NG>
__device__ __forceinline__ void cp_wait() {
    asm volatile("cp.async.wait_group %0;" :: "n"(NG) : "memory");
}
__device__ __forceinline__ void ldm_x4(uint32_t* r, uint32_t addr) {
    asm volatile("ldmatrix.sync.aligned.m8n8.x4.shared.b16 {%0,%1,%2,%3}, [%4];"
                 : "=r"(r[0]), "=r"(r[1]), "=r"(r[2]), "=r"(r[3]) : "r"(addr));
}
__device__ __forceinline__ void mma_tf32(float* c, const uint32_t* a, const uint32_t* b) {
    asm volatile("mma.sync.aligned.m16n8k8.row.col.f32.tf32.tf32.f32 "
                 "{%0,%1,%2,%3}, {%4,%5,%6,%7}, {%8,%9}, {%0,%1,%2,%3};"
                 : "+f"(c[0]), "+f"(c[1]), "+f"(c[2]), "+f"(c[3])
                 : "r"(a[0]), "r"(a[1]), "r"(a[2]), "r"(a[3]), "r"(b[0]), "r"(b[1]));
}
__device__ __forceinline__ float tf32_round(float x) {
    uint32_t u;
    asm("cvt.rna.tf32.f32 %0, %1;" : "=r"(u) : "f"(x));
    return __uint_as_float(u);
}

// ---------------- triu decode ----------------
__device__ __forceinline__ int2 triu_decode(int p, int C, int k)
{
    int Cm = C - k;
    float t = 2.0f*Cm + 1.0f;
    int a = (int)((t - sqrtf(t*t - 8.0f*(float)p)) * 0.5f);
    if (a < 0) a = 0;
    if (a > Cm-1) a = Cm-1;
    while (a > 0 && a*Cm - (a*(a-1))/2 > p) --a;
    while ((a+1)*Cm - ((a+1)*a)/2 <= p) ++a;
    int b = a + k + (p - (a*Cm - (a*(a-1))/2));
    return make_int2(a, b);
}

// ---------------- stage 0: weight transpose + tf32 rounding ----------------
__global__ __launch_bounds__(256)
void prep_weight(const float* __restrict__ W, float* __restrict__ T, int K, int N)
{
    __shared__ float tile[32][33];
    int kb = blockIdx.y*32, nb = blockIdx.x*32;
    int tx = threadIdx.x & 31, ty = threadIdx.x >> 5;   // 32 x 8
    for (int i = ty; i < 32; i += 8) {
        int k = kb + i, n = nb + tx;
        tile[i][tx] = (k < K && n < N) ? W[(size_t)k*N + n] : 0.f;
    }
    __syncthreads();
    for (int i = ty; i < 32; i += 8) {
        int n = nb + i, k = kb + tx;
        if (n < N && k < K)
            T[(size_t)n*K + k] = tf32_round(tile[tx][i]);
    }
}

// ---------------- stage 1: feature construction ----------------
__global__ __launch_bounds__(256)
void build_features(const float* __restrict__ xs, const float* __restrict__ xv)
{
    const int n = blockIdx.x;
    __shared__ float s[kC0];
    __shared__ float v[kC1][3];
    const int t = threadIdx.x;
    if (t < kC0) s[t] = xs[(size_t)n*kC0 + t];
    if (t >= 128 && t < 128 + kC1*3) ((float*)v)[t-128] = xv[(size_t)n*kC1*3 + (t-128)];
    __syncthreads();

    const float RS2 = 0.70710678118654752f;
    const float RS3 = 0.57735026918962576f;
    const float S6  = 0.40824829046386302f;

    float* f0  = d_f0  + (size_t)n*kM0;
    float* f0t = d_f0t + (size_t)n*kM0;

    if (t < kC0) { float x = s[t]; f0[t] = x; f0t[t] = tf32_round(x); }
    for (int p = t; p < kP0; p += 256) {
        int2 ab = triu_decode(p, kC0, 0);
        float c = (ab.x == ab.y) ? RS2 : 1.0f;
        float x = s[ab.x]*s[ab.y]*c;
        f0[kC0 + p] = x; f0t[kC0 + p] = tf32_round(x);
    }
    for (int p = t; p < kP1; p += 256) {
        int2 ab = triu_decode(p, kC1, 0);
        float c = ((ab.x == ab.y) ? RS2 : 1.0f) * RS3;
        float x = (v[ab.x][0]*v[ab.y][0] + v[ab.x][1]*v[ab.y][1] + v[ab.x][2]*v[ab.y][2]) * c;
        f0[kC0 + kP0 + p] = x; f0t[kC0 + kP0 + p] = tf32_round(x);
    }
    for (int c = t; c < kM1; c += 256) {
        float e0, e1, e2;
        if (c < kC1) { e0 = v[c][0]; e1 = v[c][1]; e2 = v[c][2]; }
        else {
            int cc = (c - kC1) >> 5;
            int vv = (c - kC1) & 31;
            float sc = s[cc];
            e0 = sc*v[vv][0]; e1 = sc*v[vv][1]; e2 = sc*v[vv][2];
        }
        size_t idx = (size_t)n*kM1 + c;
        d_f1[0][idx] = e0; d_f1[1][idx] = e1; d_f1[2][idx] = e2;
    }
    for (int p = t; p < kA1; p += 256) {
        int2 ab = triu_decode(p, kC1, 1);
        float ux = v[ab.x][0], uy = v[ab.x][1], uz = v[ab.x][2];
        float wx = v[ab.y][0], wy = v[ab.y][1], wz = v[ab.y][2];
        size_t idx = (size_t)n*kA1 + p;
        d_f1e[0][idx] = (uy*wz - uz*wy) * RS2;
        d_f1e[1][idx] = (uz*wx - ux*wz) * RS2;
        d_f1e[2][idx] = (ux*wy - uy*wx) * RS2;
    }
    for (int p = t; p < kP1; p += 256) {
        int2 ab = triu_decode(p, kC1, 0);
        float c = (ab.x == ab.y) ? RS2 : 1.0f;
        float ax = v[ab.x][0], ay = v[ab.x][1], az = v[ab.x][2];
        float bx = v[ab.y][0], by = v[ab.y][1], bz = v[ab.y][2];
        size_t idx = (size_t)n*kP1 + p;
        d_f2[0][idx] = RS2*(ax*by + ay*bx)*c;
        d_f2[1][idx] = RS2*(ay*bz + az*by)*c;
        d_f2[2][idx] = RS2*(ax*bz + az*bx)*c;
        d_f2[3][idx] = RS2*(ax*bx - ay*by)*c;
        d_f2[4][idx] = S6*(-ax*bx - ay*by + 2.0f*az*bz)*c;
    }
}

// ---- tf32 MMA GEMM: 128x256 tile, 512 thr, BK=32 (fp32), 3-stage cp.async pipeline ----
constexpr int kRowStride  = 144;                    // 128B data + 16B pad
constexpr int kATileBytes = 128 * kRowStride;       // 18432
constexpr int kBTileBytes = 256 * kRowStride;       // 36864
constexpr int kBufBytes   = kATileBytes + kBTileBytes; // 55296
constexpr int kStages     = 3;
constexpr int kGemmSmem   = kStages * kBufBytes;    // 165888

template<bool SILU>
__global__ __launch_bounds__(512, 1)
void mma_gemm(const float* __restrict__ A, const float* __restrict__ B,
              float* __restrict__ Cout, int K, int Nglob)
{
    extern __shared__ char smem[];
    const uint32_t sbase = smem_u32(smem);
    const int tid  = threadIdx.x;
    const int wid  = tid >> 5, lane = tid & 31;
    const int m0   = blockIdx.y * 128;
    const int n0   = blockIdx.x * 256;
    const int wm   = (wid & 1) * 64;      // 2 M-warps
    const int wn   = (wid >> 1) * 32;     // 8 N-warps

    float acc[4][4][4];
    #pragma unroll
    for (int i = 0; i < 4; i++)
        #pragma unroll
        for (int j = 0; j < 4; j++)
            #pragma unroll
            for (int q = 0; q < 4; q++) acc[i][j][q] = 0.0f;

    const int nChunks = (K + 31) / 32;    // 84

    // ---- loader: 3072 x 16B per chunk (A 1024 | B 2048), rows of 128B ----
    auto load_chunk = [&](int c) {
        const uint32_t db = sbase + (uint32_t)(c % kStages) * kBufBytes;
        const int k0 = c * 32;
        #pragma unroll
        for (int t = 0; t < 6; t++) {
            int idx = t * 512 + tid;            // 0..3071
            int kc  = idx & 7;
            int gk  = k0 + kc * 4;              // 4 floats per 16B
            bool kok = gk < K;                  // K % 4 == 0
            const float* src;
            uint32_t dst;
            bool ok;
            if (idx < 1024) {
                int row = idx >> 3;             // 0..127
                dst = db + (uint32_t)row * kRowStride + kc * 16;
                src = A + (size_t)(m0 + row) * K + (kok ? gk : 0);
                ok  = kok;
            } else {
                int rem = idx - 1024;           // 0..2047
                int row = rem >> 3;             // 0..255
                dst = db + (uint32_t)kATileBytes + (uint32_t)row * kRowStride + kc * 16;
                int gn = n0 + row;
                bool nok = gn < Nglob;
                src = B + (size_t)(nok ? gn : 0) * K + (kok ? gk : 0);
                ok  = kok && nok;
            }
            cp16(dst, src, ok);
        }
        cp_commit();
    };

    load_chunk(0);
    load_chunk(1);

    for (int c = 0; c < nChunks; c++) {
        if (c + 1 < nChunks) cp_wait<1>(); else cp_wait<0>();
        __syncthreads();
        if (c + 2 < nChunks) load_chunk(c + 2);

        const uint32_t db = sbase + (uint32_t)(c % kStages) * kBufBytes;
        const uint32_t aT = db;
        const uint32_t bT = db + kATileBytes;

        #pragma unroll
        for (int s = 0; s < 4; s++) {          // four k8 steps in BK=32
            uint32_t af[4][4], bf[4][2];
            // A frags: 16x8 fp32 tile == 16x16 b16 -> ldmatrix.x4 directly
            const int arow = wm + (lane & 15);
            const int acol = s * 32 + (lane >> 4) * 16;    // bytes
            #pragma unroll
            for (int mt = 0; mt < 4; mt++) {
                uint32_t off = (uint32_t)(arow + mt*16) * kRowStride + acol;
                ldm_x4(af[mt], aT + off);
            }
            // B frags: one x4 covers two n-tiles x two k-halves
            const int bg  = lane >> 3;
            const int br  = lane & 7;
            const int bnt = bg >> 1;
            const int bkh = (bg & 1) * 16;
            #pragma unroll
            for (int np = 0; np < 2; np++) {
                uint32_t off = (uint32_t)(wn + (np*2 + bnt)*8 + br) * kRowStride
                             + s*32 + bkh;
                ldm_x4(&bf[np*2][0], bT + off);
            }
            #pragma unroll
            for (int mt = 0; mt < 4; mt++)
                #pragma unroll
                for (int nt = 0; nt < 4; nt++)
                    mma_tf32(acc[mt][nt], af[mt], bf[nt]);
        }
    }

    // ---- epilogue ----
    #pragma unroll
    for (int mt = 0; mt < 4; mt++) {
        #pragma unroll
        for (int nt = 0; nt < 4; nt++) {
            int row = m0 + wm + mt*16 + (lane >> 2);
            int col = n0 + wn + nt*8 + (lane & 3) * 2;
            #pragma unroll
            for (int half = 0; half < 2; half++) {
                int r = row + half * 8;
                float v0 = acc[mt][nt][half*2 + 0];
                float v1 = acc[mt][nt][half*2 + 1];
                if (col < Nglob) {
                    size_t o = (size_t)r * Nglob + col;
                    if (SILU) {
                        v0 = v0 / (1.0f + __expf(-v0));
                        v1 = v1 / (1.0f + __expf(-v1));
                        Cout[o]   = tf32_round(v0);   // h feeds GEMM2 as tf32
                        Cout[o+1] = tf32_round(v1);
                    } else {
                        Cout[o]   = v0;
                        Cout[o+1] = v1;
                    }
                }
            }
        }
    }
}

// ---------------- stage 5: skinny output GEMMs with fused gating ----------------
template<int OC>
__global__ __launch_bounds__(256)
void skinny_gemm(const float* __restrict__ A, const float* __restrict__ gAll, int gOff,
                 const float* __restrict__ W, float* __restrict__ out,
                 int K, int outBase, int outStride)
{
    constexpr int BR = 32, BK = 32;
    constexpr int G   = 256 / OC;
    constexpr int RPT = BR / G;
    __shared__ float As[BR][BK + 1];
    __shared__ float Ws[BK][OC];
    const int tid  = threadIdx.x;
    const int row0 = blockIdx.x * BR;
    const int col  = tid % OC;
    const int rg   = tid / OC;

    float acc[RPT];
    #pragma unroll
    for (int r = 0; r < RPT; r++) acc[r] = 0.0f;

    for (int k0 = 0; k0 < K; k0 += BK) {
        int r  = tid >> 3;
        int kc = (tid & 7) << 2;
        float4 a4 = make_float4(0.f, 0.f, 0.f, 0.f);
        if (k0 + kc + 4 <= K) {
            a4 = *reinterpret_cast<const float4*>(A + (size_t)(row0 + r)*K + k0 + kc);
            float4 g4 = *reinterpret_cast<const float4*>(
                gAll + (size_t)(row0 + r)*kG + gOff + k0 + kc);
            a4.x *= g4.x; a4.y *= g4.y; a4.z *= g4.z; a4.w *= g4.w;
        }
        As[r][kc] = a4.x; As[r][kc+1] = a4.y; As[r][kc+2] = a4.z; As[r][kc+3] = a4.w;
        for (int idx = tid; idx < BK*OC; idx += 256) {
            int kk = idx / OC, oo = idx % OC;
            Ws[kk][oo] = (k0 + kk < K) ? W[(size_t)(k0 + kk)*OC + oo] : 0.0f;
        }
        __syncthreads();
        #pragma unroll
        for (int kk = 0; kk < BK; kk++) {
            float wv = Ws[kk][col];
            #pragma unroll
            for (int rr = 0; rr < RPT; rr++)
                acc[rr] = fmaf(As[rg + rr*G][kk], wv, acc[rr]);
        }
        __syncthreads();
    }
    #pragma unroll
    for (int rr = 0; rr < RPT; rr++)
        out[(size_t)(row0 + rg + rr*G)*kOUTW + outBase + col*outStride] = acc[rr];
}

// ---------------- launch ----------------
extern "C" void kernel_launch(void* const* d_in, const int* in_sizes, int n_in,
                              void* d_out, int out_size)
{
    const float* xs  = (const float*)d_in[0];
    const float* xv  = (const float*)d_in[1];
    const float* w1  = (const float*)d_in[2];
    const float* w2  = (const float*)d_in[3];
    const float* w0  = (const float*)d_in[4];
    const float* w1o = (const float*)d_in[5];
    const float* w1e = (const float*)d_in[6];
    const float* w2e = (const float*)d_in[7];
    float* out = (float*)d_out;

    void *pf0, *pf0t, *ph, *pg, *pf1, *pf1e, *pf2, *pw1t, *pw2t;
    cudaGetSymbolAddress(&pf0,  d_f0);
    cudaGetSymbolAddress(&pf0t, d_f0t);
    cudaGetSymbolAddress(&ph,   d_h);
    cudaGetSymbolAddress(&pg,   d_g);
    cudaGetSymbolAddress(&pf1,  d_f1);
    cudaGetSymbolAddress(&pf1e, d_f1e);
    cudaGetSymbolAddress(&pf2,  d_f2);
    cudaGetSymbolAddress(&pw1t, d_w1t);
    cudaGetSymbolAddress(&pw2t, d_w2t);

    float* f0v  = (float*)pf0;
    float* f0tv = (float*)pf0t;
    float* hv   = (float*)ph;
    float* gv   = (float*)pg;
    float* f1v  = (float*)pf1;
    float* f1ev = (float*)pf1e;
    float* f2v  = (float*)pf2;
    float* w1tv = (float*)pw1t;
    float* w2tv = (float*)pw2t;

    cudaFuncSetAttribute(mma_gemm<true>,  cudaFuncAttributeMaxDynamicSharedMemorySize, kGemmSmem);
    cudaFuncSetAttribute(mma_gemm<false>, cudaFuncAttributeMaxDynamicSharedMemorySize, kGemmSmem);

    // stage 0: weight transpose + tf32 rounding
    prep_weight<<<dim3((kM0+31)/32, (kM0+31)/32), 256>>>(w1, w1tv, kM0, kM0);
    prep_weight<<<dim3((kG +31)/32, (kM0+31)/32), 256>>>(w2, w2tv, kM0, kG);

    // stage 1: features (exact f0 + tf32 copy)
    build_features<<<kN, 256>>>(xs, xv);

    // stage 2: h = tf32(silu(f0t @ W1))      [8192 x 2672]
    {
        dim3 grid((kM0 + 255)/256, kN/128);
        mma_gemm<true><<<grid, 512, kGemmSmem>>>(f0tv, w1tv, hv, kM0, kM0);
    }
    // stage 3: g = h @ W2 (fp32)             [8192 x 5776]
    {
        dim3 grid((kG + 255)/256, kN/128);
        mma_gemm<false><<<grid, 512, kGemmSmem>>>(hv, w2tv, gv, kM0, kG);
    }

    // stage 5: gated outputs into [N,288] (gate fused into A-load)
    skinny_gemm<64><<<kN/32, 256>>>(f0v, gv, 0, w0, out, kM0, 0, 1);
    for (int i = 0; i < 3; i++)
        skinny_gemm<32><<<kN/32, 256>>>(f1v + (size_t)i*kN*kM1, gv, kM0,
                                        w1o, out, kM1, 64 + i, 3);
    for (int i = 0; i < 3; i++)
        skinny_gemm<16><<<kN/32, 256>>>(f1ev + (size_t)i*kN*kA1, gv, kM0 + kM1,
                                        w1e, out, kA1, 160 + i, 3);
    for (int m = 0; m < 5; m++)
        skinny_gemm<16><<<kN/32, 256>>>(f2v + (size_t)m*kN*kP1, gv, kM0 + kM1 + kA1,
                                        w2e, out, kP1, 208 + m, 5);
}

// round 8
// speedup vs baseline: 2.8753x; 1.1378x over previous
#include <cuda_runtime.h>
#include <cuda_bf16.h>
#include <cstdint>
#include <math.h>

// ---------------- problem constants ----------------
constexpr int kN    = 8192;
constexpr int kC0   = 64;
constexpr int kC1   = 32;
constexpr int kP0   = kC0*(kC0+1)/2;      // 2080
constexpr int kP1   = kC1*(kC1+1)/2;      // 528
constexpr int kA1   = kC1*(kC1-1)/2;      // 496
constexpr int kM0   = kC0 + kP0 + kP1;    // 2672
constexpr int kM1   = kC1 + kC0*kC1;      // 2080
constexpr int kG    = kM0 + kM1 + kA1 + kP1; // 5776
constexpr int kOUTW = 64 + 32*3 + 16*3 + 16*5; // 288

// ---------------- scratch (static device globals; no allocation) ----------------
__device__ float d_f0t[(size_t)kN*kM0];   // tf32-rounded f0
__device__ float d_h  [(size_t)kN*kM0];   // tf32-rounded silu output
__device__ float d_g  [(size_t)kN*kG];
__device__ float d_f1 [3][(size_t)kN*kM1];
__device__ float d_f1e[3][(size_t)kN*kA1];
__device__ float d_f2 [5][(size_t)kN*kP1];
__device__ float d_w1t[(size_t)kM0*kM0];  // [N=2672][K=2672] K-major, tf32-rounded
__device__ float d_w2t[(size_t)kG*kM0];   // [N=5776][K=2672] K-major, tf32-rounded

// ---------------- PTX helpers (family-portable: sm_80+ mma.sync / cp.async) ----------------
__device__ __forceinline__ uint32_t smem_u32(const void* p) {
    uint32_t a;
    asm("{ .reg .u64 t; cvta.to.shared.u64 t, %1; cvt.u32.u64 %0, t; }" : "=r"(a) : "l"(p));
    return a;
}
__device__ __forceinline__ void cp16(uint32_t dst, const void* src, bool pred) {
    int sz = pred ? 16 : 0;
    asm volatile("cp.async.cg.shared.global [%0], [%1], 16, %2;"
                 :: "r"(dst), "l"(src), "r"(sz) : "memory");
}
__device__ __forceinline__ void cp_commit() {
    asm volatile("cp.async.commit_group;" ::: "memory");
}
template<int NG>
__device__ __forceinline__ void cp_wait() {
    asm volatile("cp.async.wait_group %0;" :: "n"(NG) : "memory");
}
__device__ __forceinline__ void ldm_x4(uint32_t* r, uint32_t addr) {
    asm volatile("ldmatrix.sync.aligned.m8n8.x4.shared.b16 {%0,%1,%2,%3}, [%4];"
                 : "=r"(r[0]), "=r"(r[1]), "=r"(r[2]), "=r"(r[3]) : "r"(addr));
}
__device__ __forceinline__ void mma_tf32(float* c, const uint32_t* a, const uint32_t* b) {
    asm volatile("mma.sync.aligned.m16n8k8.row.col.f32.tf32.tf32.f32 "
                 "{%0,%1,%2,%3}, {%4,%5,%6,%7}, {%8,%9}, {%0,%1,%2,%3};"
                 : "+f"(c[0]), "+f"(c[1]), "+f"(c[2]), "+f"(c[3])
                 : "r"(a[0]), "r"(a[1]), "r"(a[2]), "r"(a[3]), "r"(b[0]), "r"(b[1]));
}
__device__ __forceinline__ float tf32_round(float x) {
    uint32_t u;
    asm("cvt.rna.tf32.f32 %0, %1;" : "=r"(u) : "f"(x));
    return __uint_as_float(u);
}

// ---------------- triu decode ----------------
__device__ __forceinline__ int2 triu_decode(int p, int C, int k)
{
    int Cm = C - k;
    float t = 2.0f*Cm + 1.0f;
    int a = (int)((t - sqrtf(t*t - 8.0f*(float)p)) * 0.5f);
    if (a < 0) a = 0;
    if (a > Cm-1) a = Cm-1;
    while (a > 0 && a*Cm - (a*(a-1))/2 > p) --a;
    while ((a+1)*Cm - ((a+1)*a)/2 <= p) ++a;
    int b = a + k + (p - (a*Cm - (a*(a-1))/2));
    return make_int2(a, b);
}

// ---------------- stage 0: weight transpose + tf32 rounding ----------------
__global__ __launch_bounds__(256)
void prep_weight(const float* __restrict__ W, float* __restrict__ T, int K, int N)
{
    __shared__ float tile[32][33];
    int kb = blockIdx.y*32, nb = blockIdx.x*32;
    int tx = threadIdx.x & 31, ty = threadIdx.x >> 5;   // 32 x 8
    for (int i = ty; i < 32; i += 8) {
        int k = kb + i, n = nb + tx;
        tile[i][tx] = (k < K && n < N) ? W[(size_t)k*N + n] : 0.f;
    }
    __syncthreads();
    for (int i = ty; i < 32; i += 8) {
        int n = nb + i, k = kb + tx;
        if (n < N && k < K)
            T[(size_t)n*K + k] = tf32_round(tile[tx][i]);
    }
}

// ---------------- stage 1: feature construction ----------------
__global__ __launch_bounds__(256)
void build_features(const float* __restrict__ xs, const float* __restrict__ xv)
{
    const int n = blockIdx.x;
    __shared__ float s[kC0];
    __shared__ float v[kC1][3];
    const int t = threadIdx.x;
    if (t < kC0) s[t] = xs[(size_t)n*kC0 + t];
    if (t >= 128 && t < 128 + kC1*3) ((float*)v)[t-128] = xv[(size_t)n*kC1*3 + (t-128)];
    __syncthreads();

    const float RS2 = 0.70710678118654752f;
    const float RS3 = 0.57735026918962576f;
    const float S6  = 0.40824829046386302f;

    float* f0t = d_f0t + (size_t)n*kM0;

    if (t < kC0) f0t[t] = tf32_round(s[t]);
    for (int p = t; p < kP0; p += 256) {
        int2 ab = triu_decode(p, kC0, 0);
        float c = (ab.x == ab.y) ? RS2 : 1.0f;
        f0t[kC0 + p] = tf32_round(s[ab.x]*s[ab.y]*c);
    }
    for (int p = t; p < kP1; p += 256) {
        int2 ab = triu_decode(p, kC1, 0);
        float c = ((ab.x == ab.y) ? RS2 : 1.0f) * RS3;
        float x = (v[ab.x][0]*v[ab.y][0] + v[ab.x][1]*v[ab.y][1] + v[ab.x][2]*v[ab.y][2]) * c;
        f0t[kC0 + kP0 + p] = tf32_round(x);
    }
    for (int c = t; c < kM1; c += 256) {
        float e0, e1, e2;
        if (c < kC1) { e0 = v[c][0]; e1 = v[c][1]; e2 = v[c][2]; }
        else {
            int cc = (c - kC1) >> 5;
            int vv = (c - kC1) & 31;
            float sc = s[cc];
            e0 = sc*v[vv][0]; e1 = sc*v[vv][1]; e2 = sc*v[vv][2];
        }
        size_t idx = (size_t)n*kM1 + c;
        d_f1[0][idx] = e0; d_f1[1][idx] = e1; d_f1[2][idx] = e2;
    }
    for (int p = t; p < kA1; p += 256) {
        int2 ab = triu_decode(p, kC1, 1);
        float ux = v[ab.x][0], uy = v[ab.x][1], uz = v[ab.x][2];
        float wx = v[ab.y][0], wy = v[ab.y][1], wz = v[ab.y][2];
        size_t idx = (size_t)n*kA1 + p;
        d_f1e[0][idx] = (uy*wz - uz*wy) * RS2;
        d_f1e[1][idx] = (uz*wx - ux*wz) * RS2;
        d_f1e[2][idx] = (ux*wy - uy*wx) * RS2;
    }
    for (int p = t; p < kP1; p += 256) {
        int2 ab = triu_decode(p, kC1, 0);
        float c = (ab.x == ab.y) ? RS2 : 1.0f;
        float ax = v[ab.x][0], ay = v[ab.x][1], az = v[ab.x][2];
        float bx = v[ab.y][0], by = v[ab.y][1], bz = v[ab.y][2];
        size_t idx = (size_t)n*kP1 + p;
        d_f2[0][idx] = RS2*(ax*by + ay*bx)*c;
        d_f2[1][idx] = RS2*(ay*bz + az*by)*c;
        d_f2[2][idx] = RS2*(ax*bz + az*bx)*c;
        d_f2[3][idx] = RS2*(ax*bx - ay*by)*c;
        d_f2[4][idx] = S6*(-ax*bx - ay*by + 2.0f*az*bz)*c;
    }
}

// ---- tf32 MMA GEMM: 128x256 tile, 512 thr, BK=32 (fp32), 3-stage cp.async pipeline ----
constexpr int kRowStride  = 144;                    // 128B data + 16B pad
constexpr int kATileBytes = 128 * kRowStride;       // 18432
constexpr int kBTileBytes = 256 * kRowStride;       // 36864
constexpr int kBufBytes   = kATileBytes + kBTileBytes; // 55296
constexpr int kStages     = 3;
constexpr int kGemmSmem   = kStages * kBufBytes;    // 165888

template<bool SILU>
__global__ __launch_bounds__(512, 1)
void mma_gemm(const float* __restrict__ A, const float* __restrict__ B,
              float* __restrict__ Cout, int K, int Nglob)
{
    extern __shared__ char smem[];
    const uint32_t sbase = smem_u32(smem);
    const int tid  = threadIdx.x;
    const int wid  = tid >> 5, lane = tid & 31;
    const int m0   = blockIdx.y * 128;
    const int n0   = blockIdx.x * 256;
    const int wm   = (wid & 1) * 64;      // 2 M-warps
    const int wn   = (wid >> 1) * 32;     // 8 N-warps

    float acc[4][4][4];
    #pragma unroll
    for (int i = 0; i < 4; i++)
        #pragma unroll
        for (int j = 0; j < 4; j++)
            #pragma unroll
            for (int q = 0; q < 4; q++) acc[i][j][q] = 0.0f;

    const int nChunks = (K + 31) / 32;    // 84

    auto load_chunk = [&](int c) {
        const uint32_t db = sbase + (uint32_t)(c % kStages) * kBufBytes;
        const int k0 = c * 32;
        #pragma unroll
        for (int t = 0; t < 6; t++) {
            int idx = t * 512 + tid;            // 0..3071
            int kc  = idx & 7;
            int gk  = k0 + kc * 4;
            bool kok = gk < K;
            const float* src;
            uint32_t dst;
            bool ok;
            if (idx < 1024) {
                int row = idx >> 3;
                dst = db + (uint32_t)row * kRowStride + kc * 16;
                src = A + (size_t)(m0 + row) * K + (kok ? gk : 0);
                ok  = kok;
            } else {
                int rem = idx - 1024;
                int row = rem >> 3;
                dst = db + (uint32_t)kATileBytes + (uint32_t)row * kRowStride + kc * 16;
                int gn = n0 + row;
                bool nok = gn < Nglob;
                src = B + (size_t)(nok ? gn : 0) * K + (kok ? gk : 0);
                ok  = kok && nok;
            }
            cp16(dst, src, ok);
        }
        cp_commit();
    };

    load_chunk(0);
    load_chunk(1);

    for (int c = 0; c < nChunks; c++) {
        if (c + 1 < nChunks) cp_wait<1>(); else cp_wait<0>();
        __syncthreads();
        if (c + 2 < nChunks) load_chunk(c + 2);

        const uint32_t db = sbase + (uint32_t)(c % kStages) * kBufBytes;
        const uint32_t aT = db;
        const uint32_t bT = db + kATileBytes;

        #pragma unroll
        for (int s = 0; s < 4; s++) {
            uint32_t af[4][4], bf[4][2];
            const int arow = wm + (lane & 15);
            const int acol = s * 32 + (lane >> 4) * 16;
            #pragma unroll
            for (int mt = 0; mt < 4; mt++) {
                uint32_t off = (uint32_t)(arow + mt*16) * kRowStride + acol;
                ldm_x4(af[mt], aT + off);
            }
            const int bg  = lane >> 3;
            const int br  = lane & 7;
            const int bnt = bg >> 1;
            const int bkh = (bg & 1) * 16;
            #pragma unroll
            for (int np = 0; np < 2; np++) {
                uint32_t off = (uint32_t)(wn + (np*2 + bnt)*8 + br) * kRowStride
                             + s*32 + bkh;
                ldm_x4(&bf[np*2][0], bT + off);
            }
            #pragma unroll
            for (int mt = 0; mt < 4; mt++)
                #pragma unroll
                for (int nt = 0; nt < 4; nt++)
                    mma_tf32(acc[mt][nt], af[mt], bf[nt]);
        }
    }

    #pragma unroll
    for (int mt = 0; mt < 4; mt++) {
        #pragma unroll
        for (int nt = 0; nt < 4; nt++) {
            int row = m0 + wm + mt*16 + (lane >> 2);
            int col = n0 + wn + nt*8 + (lane & 3) * 2;
            #pragma unroll
            for (int half = 0; half < 2; half++) {
                int r = row + half * 8;
                float v0 = acc[mt][nt][half*2 + 0];
                float v1 = acc[mt][nt][half*2 + 1];
                if (col < Nglob) {
                    size_t o = (size_t)r * Nglob + col;
                    if (SILU) {
                        v0 = v0 / (1.0f + __expf(-v0));
                        v1 = v1 / (1.0f + __expf(-v1));
                        Cout[o]   = tf32_round(v0);
                        Cout[o+1] = tf32_round(v1);
                    } else {
                        Cout[o]   = v0;
                        Cout[o+1] = v1;
                    }
                }
            }
        }
    }
}

// ---- stage 5: tensorized gated skinny GEMM (components stacked across grid.x) ----
// A tile 128 x 32 fp32 gated+tf32 in loader; W chunk transposed to [OC][32] in smem.
// grid.x = NC * 64 (comp = bx/64, 128-row block = bx%64), grid.y = column tiles.
constexpr int kSkRowStride = 144;
constexpr int kSkASize     = 128 * kSkRowStride;    // 18432

template<int OC>
__global__ __launch_bounds__(256)
void skinny_mma(const float* __restrict__ Abase, size_t compStride,
                const float* __restrict__ g, int gOff,
                const float* __restrict__ W, int ldw,
                float* __restrict__ out, int K,
                int outBase0, int outStride)
{
    __shared__ char smem[kSkASize + OC * kSkRowStride];
    const uint32_t aT = smem_u32(smem);
    const uint32_t bT = aT + kSkASize;
    const int tid  = threadIdx.x;
    const int wid  = tid >> 5, lane = tid & 31;
    const int comp = blockIdx.x >> 6;          // 64 row-blocks per component
    const int n0   = (blockIdx.x & 63) * 128;
    const int colOff = blockIdx.y * OC;        // column tile (f0 only)
    const int wm   = wid * 16;                 // 8 warps x 16 rows = 128

    const float* A = Abase + (size_t)comp * compStride;

    float acc[OC/8][4];
    #pragma unroll
    for (int j = 0; j < OC/8; j++)
        #pragma unroll
        for (int q = 0; q < 4; q++) acc[j][q] = 0.0f;

    for (int k0 = 0; k0 < K; k0 += 32) {
        __syncthreads();   // protect previous iteration's reads
        // gated A tile: 128 rows x 32 floats (1024 float4 groups)
        for (int i = tid; i < 1024; i += 256) {
            int r  = i >> 3;
            int kq = i & 7;
            int gk = k0 + kq * 4;
            float4 a4 = make_float4(0.f, 0.f, 0.f, 0.f);
            if (gk < K) {   // K % 4 == 0 for all families
                a4 = *reinterpret_cast<const float4*>(A + (size_t)(n0 + r)*K + gk);
                float4 g4 = *reinterpret_cast<const float4*>(
                    g + (size_t)(n0 + r)*kG + gOff + gk);
                a4.x = tf32_round(a4.x * g4.x);
                a4.y = tf32_round(a4.y * g4.y);
                a4.z = tf32_round(a4.z * g4.z);
                a4.w = tf32_round(a4.w * g4.w);
            }
            *reinterpret_cast<float4*>(smem + r*kSkRowStride + kq*16) = a4;
        }
        // W chunk transposed: Bs[o][k] = W[(k0+k)*ldw + colOff + o]
        for (int i = tid; i < OC*32; i += 256) {
            int k = i / OC, o = i % OC;
            float wv = (k0 + k < K) ? W[(size_t)(k0 + k)*ldw + colOff + o] : 0.f;
            *reinterpret_cast<float*>(smem + kSkASize + o*kSkRowStride + k*4) = wv;
        }
        __syncthreads();

        #pragma unroll
        for (int s = 0; s < 4; s++) {
            uint32_t af[4], bf[OC/8][2];
            const int arow = wm + (lane & 15);
            const int acol = s * 32 + (lane >> 4) * 16;
            ldm_x4(af, aT + (uint32_t)arow * kSkRowStride + acol);
            const int bg  = lane >> 3;
            const int br  = lane & 7;
            const int bnt = bg >> 1;
            const int bkh = (bg & 1) * 16;
            #pragma unroll
            for (int np = 0; np < OC/16; np++) {
                uint32_t off = (uint32_t)((np*2 + bnt)*8 + br) * kSkRowStride
                             + s*32 + bkh;
                ldm_x4(&bf[np*2][0], bT + off);
            }
            #pragma unroll
            for (int nt = 0; nt < OC/8; nt++)
                mma_tf32(acc[nt], af, bf[nt]);
        }
    }

    // epilogue: strided column placement into out[N, 288]
    #pragma unroll
    for (int nt = 0; nt < OC/8; nt++) {
        int row = n0 + wm + (lane >> 2);
        int oc  = colOff + nt*8 + (lane & 3) * 2;
        #pragma unroll
        for (int half = 0; half < 2; half++) {
            int r = row + half * 8;
            size_t o = (size_t)r * kOUTW + outBase0 + comp + (size_t)oc * outStride;
            out[o]             = acc[nt][half*2 + 0];
            out[o + outStride] = acc[nt][half*2 + 1];
        }
    }
}

// ---------------- launch ----------------
extern "C" void kernel_launch(void* const* d_in, const int* in_sizes, int n_in,
                              void* d_out, int out_size)
{
    const float* xs  = (const float*)d_in[0];
    const float* xv  = (const float*)d_in[1];
    const float* w1  = (const float*)d_in[2];
    const float* w2  = (const float*)d_in[3];
    const float* w0  = (const float*)d_in[4];
    const float* w1o = (const float*)d_in[5];
    const float* w1e = (const float*)d_in[6];
    const float* w2e = (const float*)d_in[7];
    float* out = (float*)d_out;

    void *pf0t, *ph, *pg, *pf1, *pf1e, *pf2, *pw1t, *pw2t;
    cudaGetSymbolAddress(&pf0t, d_f0t);
    cudaGetSymbolAddress(&ph,   d_h);
    cudaGetSymbolAddress(&pg,   d_g);
    cudaGetSymbolAddress(&pf1,  d_f1);
    cudaGetSymbolAddress(&pf1e, d_f1e);
    cudaGetSymbolAddress(&pf2,  d_f2);
    cudaGetSymbolAddress(&pw1t, d_w1t);
    cudaGetSymbolAddress(&pw2t, d_w2t);

    float* f0tv = (float*)pf0t;
    float* hv   = (float*)ph;
    float* gv   = (float*)pg;
    float* f1v  = (float*)pf1;
    float* f1ev = (float*)pf1e;
    float* f2v  = (float*)pf2;
    float* w1tv = (float*)pw1t;
    float* w2tv = (float*)pw2t;

    cudaFuncSetAttribute(mma_gemm<true>,  cudaFuncAttributeMaxDynamicSharedMemorySize, kGemmSmem);
    cudaFuncSetAttribute(mma_gemm<false>, cudaFuncAttributeMaxDynamicSharedMemorySize, kGemmSmem);

    // stage 0: weight transpose + tf32 rounding
    prep_weight<<<dim3((kM0+31)/32, (kM0+31)/32), 256>>>(w1, w1tv, kM0, kM0);
    prep_weight<<<dim3((kG +31)/32, (kM0+31)/32), 256>>>(w2, w2tv, kM0, kG);

    // stage 1: features
    build_features<<<kN, 256>>>(xs, xv);

    // stage 2: h = tf32(silu(f0t @ W1))      [8192 x 2672]
    {
        dim3 grid((kM0 + 255)/256, kN/128);
        mma_gemm<true><<<grid, 512, kGemmSmem>>>(f0tv, w1tv, hv, kM0, kM0);
    }
    // stage 3: g = h @ W2 (fp32)             [8192 x 5776]
    {
        dim3 grid((kG + 255)/256, kN/128);
        mma_gemm<false><<<grid, 512, kGemmSmem>>>(hv, w2tv, gv, kM0, kG);
    }

    // stage 5: tensorized gated skinny GEMMs into [N,288]
    // o0: [8192 x 2672] @ [2672 x 64], cols split into 2 tiles of 32
    skinny_mma<32><<<dim3(64, 2), 256>>>(f0tv, 0, gv, 0,
                                         w0, 64, out, kM0, 0, 1);
    // o1: 3 components stacked: [3*8192 x 2080] @ [2080 x 32]
    skinny_mma<32><<<dim3(192, 1), 256>>>(f1v, (size_t)kN*kM1, gv, kM0,
                                          w1o, 32, out, kM1, 64, 3);
    // o1e: [3*8192 x 496] @ [496 x 16]
    skinny_mma<16><<<dim3(192, 1), 256>>>(f1ev, (size_t)kN*kA1, gv, kM0 + kM1,
                                          w1e, 16, out, kA1, 160, 3);
    // o2: [5*8192 x 528] @ [528 x 16]
    skinny_mma<16><<<dim3(320, 1), 256>>>(f2v, (size_t)kN*kP1, gv, kM0 + kM1 + kA1,
                                          w2e, 16, out, kP1, 208, 5);
}

// round 9
// speedup vs baseline: 3.0454x; 1.0592x over previous
#include <cuda_runtime.h>
#include <cuda_bf16.h>
#include <cstdint>
#include <math.h>

// ---------------- problem constants ----------------
constexpr int kN    = 8192;
constexpr int kC0   = 64;
constexpr int kC1   = 32;
constexpr int kP0   = kC0*(kC0+1)/2;      // 2080
constexpr int kP1   = kC1*(kC1+1)/2;      // 528
constexpr int kA1   = kC1*(kC1-1)/2;      // 496
constexpr int kM0   = kC0 + kP0 + kP1;    // 2672
constexpr int kM1   = kC1 + kC0*kC1;      // 2080
constexpr int kG    = kM0 + kM1 + kA1 + kP1; // 5776
constexpr int kOUTW = 64 + 32*3 + 16*3 + 16*5; // 288

// ---------------- scratch (static device globals; no allocation) ----------------
__device__ float d_f0t[(size_t)kN*kM0];   // tf32-rounded f0
__device__ float d_h  [(size_t)kN*kM0];   // tf32-rounded silu output
__device__ float d_g  [(size_t)kN*kG];
__device__ float d_f1 [3][(size_t)kN*kM1];
__device__ float d_f1e[3][(size_t)kN*kA1];
__device__ float d_f2 [5][(size_t)kN*kP1];
__device__ float d_w1t[(size_t)kM0*kM0];  // [N=2672][K=2672] K-major, tf32-rounded
__device__ float d_w2t[(size_t)kG*kM0];   // [N=5776][K=2672] K-major, tf32-rounded

// ---------------- PTX helpers (family-portable: sm_80+ mma.sync / cp.async) ----------------
__device__ __forceinline__ uint32_t smem_u32(const void* p) {
    uint32_t a;
    asm("{ .reg .u64 t; cvta.to.shared.u64 t, %1; cvt.u32.u64 %0, t; }" : "=r"(a) : "l"(p));
    return a;
}
__device__ __forceinline__ void cp16(uint32_t dst, const void* src, bool pred) {
    int sz = pred ? 16 : 0;
    asm volatile("cp.async.cg.shared.global [%0], [%1], 16, %2;"
                 :: "r"(dst), "l"(src), "r"(sz) : "memory");
}
__device__ __forceinline__ void cp_commit() {
    asm volatile("cp.async.commit_group;" ::: "memory");
}
template<int NG>
__device__ __forceinline__ void cp_wait() {
    asm volatile("cp.async.wait_group %0;" :: "n"(NG) : "memory");
}
__device__ __forceinline__ void ldm_x4(uint32_t* r, uint32_t addr) {
    asm volatile("ldmatrix.sync.aligned.m8n8.x4.shared.b16 {%0,%1,%2,%3}, [%4];"
                 : "=r"(r[0]), "=r"(r[1]), "=r"(r[2]), "=r"(r[3]) : "r"(addr));
}
__device__ __forceinline__ void mma_tf32(float* c, const uint32_t* a, const uint32_t* b) {
    asm volatile("mma.sync.aligned.m16n8k8.row.col.f32.tf32.tf32.f32 "
                 "{%0,%1,%2,%3}, {%4,%5,%6,%7}, {%8,%9}, {%0,%1,%2,%3};"
                 : "+f"(c[0]), "+f"(c[1]), "+f"(c[2]), "+f"(c[3])
                 : "r"(a[0]), "r"(a[1]), "r"(a[2]), "r"(a[3]), "r"(b[0]), "r"(b[1]));
}
__device__ __forceinline__ float tf32_round(float x) {
    uint32_t u;
    asm("cvt.rna.tf32.f32 %0, %1;" : "=r"(u) : "f"(x));
    return __uint_as_float(u);
}

// ---------------- triu decode ----------------
__device__ __forceinline__ int2 triu_decode(int p, int C, int k)
{
    int Cm = C - k;
    float t = 2.0f*Cm + 1.0f;
    int a = (int)((t - sqrtf(t*t - 8.0f*(float)p)) * 0.5f);
    if (a < 0) a = 0;
    if (a > Cm-1) a = Cm-1;
    while (a > 0 && a*Cm - (a*(a-1))/2 > p) --a;
    while ((a+1)*Cm - ((a+1)*a)/2 <= p) ++a;
    int b = a + k + (p - (a*Cm - (a*(a-1))/2));
    return make_int2(a, b);
}

// ---------------- stage 0: weight transpose + tf32 rounding ----------------
__global__ __launch_bounds__(256)
void prep_weight(const float* __restrict__ W, float* __restrict__ T, int K, int N)
{
    __shared__ float tile[32][33];
    int kb = blockIdx.y*32, nb = blockIdx.x*32;
    int tx = threadIdx.x & 31, ty = threadIdx.x >> 5;   // 32 x 8
    for (int i = ty; i < 32; i += 8) {
        int k = kb + i, n = nb + tx;
        tile[i][tx] = (k < K && n < N) ? W[(size_t)k*N + n] : 0.f;
    }
    __syncthreads();
    for (int i = ty; i < 32; i += 8) {
        int n = nb + i, k = kb + tx;
        if (n < N && k < K)
            T[(size_t)n*K + k] = tf32_round(tile[tx][i]);
    }
}

// ---------------- stage 1: feature construction ----------------
__global__ __launch_bounds__(256)
void build_features(const float* __restrict__ xs, const float* __restrict__ xv)
{
    const int n = blockIdx.x;
    __shared__ float s[kC0];
    __shared__ float v[kC1][3];
    const int t = threadIdx.x;
    if (t < kC0) s[t] = xs[(size_t)n*kC0 + t];
    if (t >= 128 && t < 128 + kC1*3) ((float*)v)[t-128] = xv[(size_t)n*kC1*3 + (t-128)];
    __syncthreads();

    const float RS2 = 0.70710678118654752f;
    const float RS3 = 0.57735026918962576f;
    const float S6  = 0.40824829046386302f;

    float* f0t = d_f0t + (size_t)n*kM0;

    if (t < kC0) f0t[t] = tf32_round(s[t]);
    for (int p = t; p < kP0; p += 256) {
        int2 ab = triu_decode(p, kC0, 0);
        float c = (ab.x == ab.y) ? RS2 : 1.0f;
        f0t[kC0 + p] = tf32_round(s[ab.x]*s[ab.y]*c);
    }
    for (int p = t; p < kP1; p += 256) {
        int2 ab = triu_decode(p, kC1, 0);
        float c = ((ab.x == ab.y) ? RS2 : 1.0f) * RS3;
        float x = (v[ab.x][0]*v[ab.y][0] + v[ab.x][1]*v[ab.y][1] + v[ab.x][2]*v[ab.y][2]) * c;
        f0t[kC0 + kP0 + p] = tf32_round(x);
    }
    for (int c = t; c < kM1; c += 256) {
        float e0, e1, e2;
        if (c < kC1) { e0 = v[c][0]; e1 = v[c][1]; e2 = v[c][2]; }
        else {
            int cc = (c - kC1) >> 5;
            int vv = (c - kC1) & 31;
            float sc = s[cc];
            e0 = sc*v[vv][0]; e1 = sc*v[vv][1]; e2 = sc*v[vv][2];
        }
        size_t idx = (size_t)n*kM1 + c;
        d_f1[0][idx] = e0; d_f1[1][idx] = e1; d_f1[2][idx] = e2;
    }
    for (int p = t; p < kA1; p += 256) {
        int2 ab = triu_decode(p, kC1, 1);
        float ux = v[ab.x][0], uy = v[ab.x][1], uz = v[ab.x][2];
        float wx = v[ab.y][0], wy = v[ab.y][1], wz = v[ab.y][2];
        size_t idx = (size_t)n*kA1 + p;
        d_f1e[0][idx] = (uy*wz - uz*wy) * RS2;
        d_f1e[1][idx] = (uz*wx - ux*wz) * RS2;
        d_f1e[2][idx] = (ux*wy - uy*wx) * RS2;
    }
    for (int p = t; p < kP1; p += 256) {
        int2 ab = triu_decode(p, kC1, 0);
        float c = (ab.x == ab.y) ? RS2 : 1.0f;
        float ax = v[ab.x][0], ay = v[ab.x][1], az = v[ab.x][2];
        float bx = v[ab.y][0], by = v[ab.y][1], bz = v[ab.y][2];
        size_t idx = (size_t)n*kP1 + p;
        d_f2[0][idx] = RS2*(ax*by + ay*bx)*c;
        d_f2[1][idx] = RS2*(ay*bz + az*by)*c;
        d_f2[2][idx] = RS2*(ax*bz + az*bx)*c;
        d_f2[3][idx] = RS2*(ax*bx - ay*by)*c;
        d_f2[4][idx] = S6*(-ax*bx - ay*by + 2.0f*az*bz)*c;
    }
}

// ---- tf32 MMA GEMM: 128x128 tile, 256 thr, 2 CTAs/SM, BK=32, 3-stage pipeline ----
constexpr int kRowStride  = 144;                    // 128B data + 16B pad
constexpr int kATileBytes = 128 * kRowStride;       // 18432
constexpr int kBufBytes   = 2 * kATileBytes;        // A + B = 36864
constexpr int kStages     = 3;
constexpr int kGemmSmem   = kStages * kBufBytes;    // 110592 (x2 CTAs = 221184)

template<bool SILU>
__global__ __launch_bounds__(256, 2)
void mma_gemm(const float* __restrict__ A, const float* __restrict__ B,
              float* __restrict__ Cout, int K, int Nglob)
{
    extern __shared__ char smem[];
    const uint32_t sbase = smem_u32(smem);
    const int tid  = threadIdx.x;
    const int wid  = tid >> 5, lane = tid & 31;
    const int m0   = blockIdx.y * 128;
    const int n0   = blockIdx.x * 128;
    const int wm   = (wid & 1) * 64;      // 2 M-warps
    const int wn   = (wid >> 1) * 32;     // 4 N-warps

    float acc[4][4][4];
    #pragma unroll
    for (int i = 0; i < 4; i++)
        #pragma unroll
        for (int j = 0; j < 4; j++)
            #pragma unroll
            for (int q = 0; q < 4; q++) acc[i][j][q] = 0.0f;

    const int nChunks = (K + 31) / 32;    // 84

    // ---- loader: 2048 x 16B per chunk (A 1024 | B 1024), rows of 128B ----
    auto load_chunk = [&](int c) {
        const uint32_t db = sbase + (uint32_t)(c % kStages) * kBufBytes;
        const int k0 = c * 32;
        #pragma unroll
        for (int t = 0; t < 8; t++) {
            int idx = t * 256 + tid;            // 0..2047
            int kc  = idx & 7;
            int gk  = k0 + kc * 4;
            bool kok = gk < K;
            int row = (idx >> 3) & 127;
            const float* src;
            uint32_t dst;
            bool ok;
            if (idx < 1024) {
                dst = db + (uint32_t)row * kRowStride + kc * 16;
                src = A + (size_t)(m0 + row) * K + (kok ? gk : 0);
                ok  = kok;
            } else {
                dst = db + (uint32_t)kATileBytes + (uint32_t)row * kRowStride + kc * 16;
                int gn = n0 + row;
                bool nok = gn < Nglob;
                src = B + (size_t)(nok ? gn : 0) * K + (kok ? gk : 0);
                ok  = kok && nok;
            }
            cp16(dst, src, ok);
        }
        cp_commit();
    };

    load_chunk(0);
    load_chunk(1);

    for (int c = 0; c < nChunks; c++) {
        if (c + 1 < nChunks) cp_wait<1>(); else cp_wait<0>();
        __syncthreads();
        if (c + 2 < nChunks) load_chunk(c + 2);

        const uint32_t db = sbase + (uint32_t)(c % kStages) * kBufBytes;
        const uint32_t aT = db;
        const uint32_t bT = db + kATileBytes;

        #pragma unroll
        for (int s = 0; s < 4; s++) {
            uint32_t af[4][4], bf[4][2];
            const int arow = wm + (lane & 15);
            const int acol = s * 32 + (lane >> 4) * 16;
            #pragma unroll
            for (int mt = 0; mt < 4; mt++) {
                uint32_t off = (uint32_t)(arow + mt*16) * kRowStride + acol;
                ldm_x4(af[mt], aT + off);
            }
            const int bg  = lane >> 3;
            const int br  = lane & 7;
            const int bnt = bg >> 1;
            const int bkh = (bg & 1) * 16;
            #pragma unroll
            for (int np = 0; np < 2; np++) {
                uint32_t off = (uint32_t)(wn + (np*2 + bnt)*8 + br) * kRowStride
                             + s*32 + bkh;
                ldm_x4(&bf[np*2][0], bT + off);
            }
            #pragma unroll
            for (int mt = 0; mt < 4; mt++)
                #pragma unroll
                for (int nt = 0; nt < 4; nt++)
                    mma_tf32(acc[mt][nt], af[mt], bf[nt]);
        }
    }

    // ---- epilogue ----
    #pragma unroll
    for (int mt = 0; mt < 4; mt++) {
        #pragma unroll
        for (int nt = 0; nt < 4; nt++) {
            int row = m0 + wm + mt*16 + (lane >> 2);
            int col = n0 + wn + nt*8 + (lane & 3) * 2;
            #pragma unroll
            for (int half = 0; half < 2; half++) {
                int r = row + half * 8;
                float v0 = acc[mt][nt][half*2 + 0];
                float v1 = acc[mt][nt][half*2 + 1];
                if (col < Nglob) {
                    size_t o = (size_t)r * Nglob + col;
                    if (SILU) {
                        v0 = v0 / (1.0f + __expf(-v0));
                        v1 = v1 / (1.0f + __expf(-v1));
                        Cout[o]   = tf32_round(v0);
                        Cout[o+1] = tf32_round(v1);
                    } else {
                        Cout[o]   = v0;
                        Cout[o+1] = v1;
                    }
                }
            }
        }
    }
}

// ---- stage 5: tensorized gated skinny GEMM (components stacked across grid.x) ----
constexpr int kSkRowStride = 144;
constexpr int kSkASize     = 128 * kSkRowStride;    // 18432

template<int OC>
__global__ __launch_bounds__(256)
void skinny_mma(const float* __restrict__ Abase, size_t compStride,
                const float* __restrict__ g, int gOff,
                const float* __restrict__ W, int ldw,
                float* __restrict__ out, int K,
                int outBase0, int outStride)
{
    __shared__ char smem[kSkASize + OC * kSkRowStride];
    const uint32_t aT = smem_u32(smem);
    const uint32_t bT = aT + kSkASize;
    const int tid  = threadIdx.x;
    const int wid  = tid >> 5, lane = tid & 31;
    const int comp = blockIdx.x >> 6;          // 64 row-blocks per component
    const int n0   = (blockIdx.x & 63) * 128;
    const int colOff = blockIdx.y * OC;        // column tile (f0 only)
    const int wm   = wid * 16;                 // 8 warps x 16 rows = 128

    const float* A = Abase + (size_t)comp * compStride;

    float acc[OC/8][4];
    #pragma unroll
    for (int j = 0; j < OC/8; j++)
        #pragma unroll
        for (int q = 0; q < 4; q++) acc[j][q] = 0.0f;

    for (int k0 = 0; k0 < K; k0 += 32) {
        __syncthreads();
        for (int i = tid; i < 1024; i += 256) {
            int r  = i >> 3;
            int kq = i & 7;
            int gk = k0 + kq * 4;
            float4 a4 = make_float4(0.f, 0.f, 0.f, 0.f);
            if (gk < K) {
                a4 = *reinterpret_cast<const float4*>(A + (size_t)(n0 + r)*K + gk);
                float4 g4 = *reinterpret_cast<const float4*>(
                    g + (size_t)(n0 + r)*kG + gOff + gk);
                a4.x = tf32_round(a4.x * g4.x);
                a4.y = tf32_round(a4.y * g4.y);
                a4.z = tf32_round(a4.z * g4.z);
                a4.w = tf32_round(a4.w * g4.w);
            }
            *reinterpret_cast<float4*>(smem + r*kSkRowStride + kq*16) = a4;
        }
        for (int i = tid; i < OC*32; i += 256) {
            int k = i / OC, o = i % OC;
            float wv = (k0 + k < K) ? W[(size_t)(k0 + k)*ldw + colOff + o] : 0.f;
            *reinterpret_cast<float*>(smem + kSkASize + o*kSkRowStride + k*4) = wv;
        }
        __syncthreads();

        #pragma unroll
        for (int s = 0; s < 4; s++) {
            uint32_t af[4], bf[OC/8][2];
            const int arow = wm + (lane & 15);
            const int acol = s * 32 + (lane >> 4) * 16;
            ldm_x4(af, aT + (uint32_t)arow * kSkRowStride + acol);
            const int bg  = lane >> 3;
            const int br  = lane & 7;
            const int bnt = bg >> 1;
            const int bkh = (bg & 1) * 16;
            #pragma unroll
            for (int np = 0; np < OC/16; np++) {
                uint32_t off = (uint32_t)((np*2 + bnt)*8 + br) * kSkRowStride
                             + s*32 + bkh;
                ldm_x4(&bf[np*2][0], bT + off);
            }
            #pragma unroll
            for (int nt = 0; nt < OC/8; nt++)
                mma_tf32(acc[nt], af, bf[nt]);
        }
    }

    #pragma unroll
    for (int nt = 0; nt < OC/8; nt++) {
        int row = n0 + wm + (lane >> 2);
        int oc  = colOff + nt*8 + (lane & 3) * 2;
        #pragma unroll
        for (int half = 0; half < 2; half++) {
            int r = row + half * 8;
            size_t o = (size_t)r * kOUTW + outBase0 + comp + (size_t)oc * outStride;
            out[o]             = acc[nt][half*2 + 0];
            out[o + outStride] = acc[nt][half*2 + 1];
        }
    }
}

// ---------------- launch ----------------
extern "C" void kernel_launch(void* const* d_in, const int* in_sizes, int n_in,
                              void* d_out, int out_size)
{
    const float* xs  = (const float*)d_in[0];
    const float* xv  = (const float*)d_in[1];
    const float* w1  = (const float*)d_in[2];
    const float* w2  = (const float*)d_in[3];
    const float* w0  = (const float*)d_in[4];
    const float* w1o = (const float*)d_in[5];
    const float* w1e = (const float*)d_in[6];
    const float* w2e = (const float*)d_in[7];
    float* out = (float*)d_out;

    void *pf0t, *ph, *pg, *pf1, *pf1e, *pf2, *pw1t, *pw2t;
    cudaGetSymbolAddress(&pf0t, d_f0t);
    cudaGetSymbolAddress(&ph,   d_h);
    cudaGetSymbolAddress(&pg,   d_g);
    cudaGetSymbolAddress(&pf1,  d_f1);
    cudaGetSymbolAddress(&pf1e, d_f1e);
    cudaGetSymbolAddress(&pf2,  d_f2);
    cudaGetSymbolAddress(&pw1t, d_w1t);
    cudaGetSymbolAddress(&pw2t, d_w2t);

    float* f0tv = (float*)pf0t;
    float* hv   = (float*)ph;
    float* gv   = (float*)pg;
    float* f1v  = (float*)pf1;
    float* f1ev = (float*)pf1e;
    float* f2v  = (float*)pf2;
    float* w1tv = (float*)pw1t;
    float* w2tv = (float*)pw2t;

    cudaFuncSetAttribute(mma_gemm<true>,  cudaFuncAttributeMaxDynamicSharedMemorySize, kGemmSmem);
    cudaFuncSetAttribute(mma_gemm<false>, cudaFuncAttributeMaxDynamicSharedMemorySize, kGemmSmem);

    // stage 0: weight transpose + tf32 rounding
    prep_weight<<<dim3((kM0+31)/32, (kM0+31)/32), 256>>>(w1, w1tv, kM0, kM0);
    prep_weight<<<dim3((kG +31)/32, (kM0+31)/32), 256>>>(w2, w2tv, kM0, kG);

    // stage 1: features
    build_features<<<kN, 256>>>(xs, xv);

    // stage 2: h = tf32(silu(f0t @ W1))      [8192 x 2672]
    {
        dim3 grid((kM0 + 127)/128, kN/128);
        mma_gemm<true><<<grid, 256, kGemmSmem>>>(f0tv, w1tv, hv, kM0, kM0);
    }
    // stage 3: g = h @ W2 (fp32)             [8192 x 5776]
    {
        dim3 grid((kG + 127)/128, kN/128);
        mma_gemm<false><<<grid, 256, kGemmSmem>>>(hv, w2tv, gv, kM0, kG);
    }

    // stage 5: tensorized gated skinny GEMMs into [N,288]
    skinny_mma<32><<<dim3(64, 2), 256>>>(f0tv, 0, gv, 0,
                                         w0, 64, out, kM0, 0, 1);
    skinny_mma<32><<<dim3(192, 1), 256>>>(f1v, (size_t)kN*kM1, gv, kM0,
                                          w1o, 32, out, kM1, 64, 3);
    skinny_mma<16><<<dim3(192, 1), 256>>>(f1ev, (size_t)kN*kA1, gv, kM0 + kM1,
                                          w1e, 16, out, kA1, 160, 3);
    skinny_mma<16><<<dim3(320, 1), 256>>>(f2v, (size_t)kN*kP1, gv, kM0 + kM1 + kA1,
                                          w2e, 16, out, kP1, 208, 5);
}

// round 10
// speedup vs baseline: 3.7198x; 1.2215x over previous
#include <cuda_runtime.h>
#include <cuda_bf16.h>
#include <cstdint>
#include <math.h>

// ---------------- problem constants ----------------
constexpr int kN    = 8192;
constexpr int kC0   = 64;
constexpr int kC1   = 32;
constexpr int kP0   = kC0*(kC0+1)/2;      // 2080
constexpr int kP1   = kC1*(kC1+1)/2;      // 528
constexpr int kA1   = kC1*(kC1-1)/2;      // 496
constexpr int kM0   = kC0 + kP0 + kP1;    // 2672
constexpr int kM1   = kC1 + kC0*kC1;      // 2080
constexpr int kG    = kM0 + kM1 + kA1 + kP1; // 5776
constexpr int kOUTW = 64 + 32*3 + 16*3 + 16*5; // 288

// ---------------- scratch (static device globals; no allocation) ----------------
__device__ float d_f0t[(size_t)kN*kM0];
__device__ float d_h  [(size_t)kN*kM0];
__device__ float d_g  [(size_t)kN*kG];
__device__ float d_f1 [3][(size_t)kN*kM1];
__device__ float d_f1e[3][(size_t)kN*kA1];
__device__ float d_f2 [5][(size_t)kN*kP1];
__device__ float d_w1t[(size_t)kM0*kM0];
__device__ float d_w2t[(size_t)kG*kM0];

// ---------------- PTX helpers (family-portable: sm_80+ mma.sync / cp.async) ----------------
__device__ __forceinline__ uint32_t smem_u32(const void* p) {
    uint32_t a;
    asm("{ .reg .u64 t; cvta.to.shared.u64 t, %1; cvt.u32.u64 %0, t; }" : "=r"(a) : "l"(p));
    return a;
}
__device__ __forceinline__ void cp16(uint32_t dst, const void* src, bool pred) {
    int sz = pred ? 16 : 0;
    asm volatile("cp.async.cg.shared.global [%0], [%1], 16, %2;"
                 :: "r"(dst), "l"(src), "r"(sz) : "memory");
}
__device__ __forceinline__ void cp_commit() {
    asm volatile("cp.async.commit_group;" ::: "memory");
}
template<int NG>
__device__ __forceinline__ void cp_wait() {
    asm volatile("cp.async.wait_group %0;" :: "n"(NG) : "memory");
}
__device__ __forceinline__ void ldm_x4(uint32_t* r, uint32_t addr) {
    asm volatile("ldmatrix.sync.aligned.m8n8.x4.shared.b16 {%0,%1,%2,%3}, [%4];"
                 : "=r"(r[0]), "=r"(r[1]), "=r"(r[2]), "=r"(r[3]) : "r"(addr));
}
__device__ __forceinline__ void mma_tf32(float* c, const uint32_t* a, const uint32_t* b) {
    asm volatile("mma.sync.aligned.m16n8k8.row.col.f32.tf32.tf32.f32 "
                 "{%0,%1,%2,%3}, {%4,%5,%6,%7}, {%8,%9}, {%0,%1,%2,%3};"
                 : "+f"(c[0]), "+f"(c[1]), "+f"(c[2]), "+f"(c[3])
                 : "r"(a[0]), "r"(a[1]), "r"(a[2]), "r"(a[3]), "r"(b[0]), "r"(b[1]));
}
__device__ __forceinline__ float tf32_round(float x) {
    uint32_t u;
    asm("cvt.rna.tf32.f32 %0, %1;" : "=r"(u) : "f"(x));
    return __uint_as_float(u);
}

// ---------------- triu decode ----------------
__device__ __forceinline__ int2 triu_decode(int p, int C, int k)
{
    int Cm = C - k;
    float t = 2.0f*Cm + 1.0f;
    int a = (int)((t - sqrtf(t*t - 8.0f*(float)p)) * 0.5f);
    if (a < 0) a = 0;
    if (a > Cm-1) a = Cm-1;
    while (a > 0 && a*Cm - (a*(a-1))/2 > p) --a;
    while ((a+1)*Cm - ((a+1)*a)/2 <= p) ++a;
    int b = a + k + (p - (a*Cm - (a*(a-1))/2));
    return make_int2(a, b);
}

// ---------------- stage 0: weight transpose + tf32 rounding ----------------
__global__ __launch_bounds__(256)
void prep_weight(const float* __restrict__ W, float* __restrict__ T, int K, int N)
{
    __shared__ float tile[32][33];
    int kb = blockIdx.y*32, nb = blockIdx.x*32;
    int tx = threadIdx.x & 31, ty = threadIdx.x >> 5;
    for (int i = ty; i < 32; i += 8) {
        int k = kb + i, n = nb + tx;
        tile[i][tx] = (k < K && n < N) ? W[(size_t)k*N + n] : 0.f;
    }
    __syncthreads();
    for (int i = ty; i < 32; i += 8) {
        int n = nb + i, k = kb + tx;
        if (n < N && k < K)
            T[(size_t)n*K + k] = tf32_round(tile[tx][i]);
    }
}

// ---------------- stage 1: feature construction ----------------
__global__ __launch_bounds__(256)
void build_features(const float* __restrict__ xs, const float* __restrict__ xv)
{
    const int n = blockIdx.x;
    __shared__ float s[kC0];
    __shared__ float v[kC1][3];
    const int t = threadIdx.x;
    if (t < kC0) s[t] = xs[(size_t)n*kC0 + t];
    if (t >= 128 && t < 128 + kC1*3) ((float*)v)[t-128] = xv[(size_t)n*kC1*3 + (t-128)];
    __syncthreads();

    const float RS2 = 0.70710678118654752f;
    const float RS3 = 0.57735026918962576f;
    const float S6  = 0.40824829046386302f;

    float* f0t = d_f0t + (size_t)n*kM0;

    if (t < kC0) f0t[t] = tf32_round(s[t]);
    for (int p = t; p < kP0; p += 256) {
        int2 ab = triu_decode(p, kC0, 0);
        float c = (ab.x == ab.y) ? RS2 : 1.0f;
        f0t[kC0 + p] = tf32_round(s[ab.x]*s[ab.y]*c);
    }
    for (int p = t; p < kP1; p += 256) {
        int2 ab = triu_decode(p, kC1, 0);
        float c = ((ab.x == ab.y) ? RS2 : 1.0f) * RS3;
        float x = (v[ab.x][0]*v[ab.y][0] + v[ab.x][1]*v[ab.y][1] + v[ab.x][2]*v[ab.y][2]) * c;
        f0t[kC0 + kP0 + p] = tf32_round(x);
    }
    for (int c = t; c < kM1; c += 256) {
        float e0, e1, e2;
        if (c < kC1) { e0 = v[c][0]; e1 = v[c][1]; e2 = v[c][2]; }
        else {
            int cc = (c - kC1) >> 5;
            int vv = (c - kC1) & 31;
            float sc = s[cc];
            e0 = sc*v[vv][0]; e1 = sc*v[vv][1]; e2 = sc*v[vv][2];
        }
        size_t idx = (size_t)n*kM1 + c;
        d_f1[0][idx] = e0; d_f1[1][idx] = e1; d_f1[2][idx] = e2;
    }
    for (int p = t; p < kA1; p += 256) {
        int2 ab = triu_decode(p, kC1, 1);
        float ux = v[ab.x][0], uy = v[ab.x][1], uz = v[ab.x][2];
        float wx = v[ab.y][0], wy = v[ab.y][1], wz = v[ab.y][2];
        size_t idx = (size_t)n*kA1 + p;
        d_f1e[0][idx] = (uy*wz - uz*wy) * RS2;
        d_f1e[1][idx] = (uz*wx - ux*wz) * RS2;
        d_f1e[2][idx] = (ux*wy - uy*wx) * RS2;
    }
    for (int p = t; p < kP1; p += 256) {
        int2 ab = triu_decode(p, kC1, 0);
        float c = (ab.x == ab.y) ? RS2 : 1.0f;
        float ax = v[ab.x][0], ay = v[ab.x][1], az = v[ab.x][2];
        float bx = v[ab.y][0], by = v[ab.y][1], bz = v[ab.y][2];
        size_t idx = (size_t)n*kP1 + p;
        d_f2[0][idx] = RS2*(ax*by + ay*bx)*c;
        d_f2[1][idx] = RS2*(ay*bz + az*by)*c;
        d_f2[2][idx] = RS2*(ax*bz + az*bx)*c;
        d_f2[3][idx] = RS2*(ax*bx - ay*by)*c;
        d_f2[4][idx] = S6*(-ax*bx - ay*by + 2.0f*az*bz)*c;
    }
}

// ---- tf32 MMA GEMM: 128x128 tile, 256 thr, 2 CTAs/SM, BK=32, 3-stage pipeline ----
constexpr int kRowStride  = 144;
constexpr int kATileBytes = 128 * kRowStride;
constexpr int kBufBytes   = 2 * kATileBytes;
constexpr int kStages     = 3;
constexpr int kGemmSmem   = kStages * kBufBytes;    // 110592

template<bool SILU>
__global__ __launch_bounds__(256, 2)
void mma_gemm(const float* __restrict__ A, const float* __restrict__ B,
              float* __restrict__ Cout, int K, int Nglob)
{
    extern __shared__ char smem[];
    const uint32_t sbase = smem_u32(smem);
    const int tid  = threadIdx.x;
    const int wid  = tid >> 5, lane = tid & 31;
    const int m0   = blockIdx.y * 128;
    const int n0   = blockIdx.x * 128;
    const int wm   = (wid & 1) * 64;
    const int wn   = (wid >> 1) * 32;

    float acc[4][4][4];
    #pragma unroll
    for (int i = 0; i < 4; i++)
        #pragma unroll
        for (int j = 0; j < 4; j++)
            #pragma unroll
            for (int q = 0; q < 4; q++) acc[i][j][q] = 0.0f;

    const int nChunks = (K + 31) / 32;

    auto load_chunk = [&](int c) {
        const uint32_t db = sbase + (uint32_t)(c % kStages) * kBufBytes;
        const int k0 = c * 32;
        #pragma unroll
        for (int t = 0; t < 8; t++) {
            int idx = t * 256 + tid;
            int kc  = idx & 7;
            int gk  = k0 + kc * 4;
            bool kok = gk < K;
            int row = (idx >> 3) & 127;
            const float* src;
            uint32_t dst;
            bool ok;
            if (idx < 1024) {
                dst = db + (uint32_t)row * kRowStride + kc * 16;
                src = A + (size_t)(m0 + row) * K + (kok ? gk : 0);
                ok  = kok;
            } else {
                dst = db + (uint32_t)kATileBytes + (uint32_t)row * kRowStride + kc * 16;
                int gn = n0 + row;
                bool nok = gn < Nglob;
                src = B + (size_t)(nok ? gn : 0) * K + (kok ? gk : 0);
                ok  = kok && nok;
            }
            cp16(dst, src, ok);
        }
        cp_commit();
    };

    load_chunk(0);
    load_chunk(1);

    for (int c = 0; c < nChunks; c++) {
        if (c + 1 < nChunks) cp_wait<1>(); else cp_wait<0>();
        __syncthreads();
        if (c + 2 < nChunks) load_chunk(c + 2);

        const uint32_t db = sbase + (uint32_t)(c % kStages) * kBufBytes;
        const uint32_t aT = db;
        const uint32_t bT = db + kATileBytes;

        #pragma unroll
        for (int s = 0; s < 4; s++) {
            uint32_t af[4][4], bf[4][2];
            const int arow = wm + (lane & 15);
            const int acol = s * 32 + (lane >> 4) * 16;
            #pragma unroll
            for (int mt = 0; mt < 4; mt++) {
                uint32_t off = (uint32_t)(arow + mt*16) * kRowStride + acol;
                ldm_x4(af[mt], aT + off);
            }
            const int bg  = lane >> 3;
            const int br  = lane & 7;
            const int bnt = bg >> 1;
            const int bkh = (bg & 1) * 16;
            #pragma unroll
            for (int np = 0; np < 2; np++) {
                uint32_t off = (uint32_t)(wn + (np*2 + bnt)*8 + br) * kRowStride
                             + s*32 + bkh;
                ldm_x4(&bf[np*2][0], bT + off);
            }
            #pragma unroll
            for (int mt = 0; mt < 4; mt++)
                #pragma unroll
                for (int nt = 0; nt < 4; nt++)
                    mma_tf32(acc[mt][nt], af[mt], bf[nt]);
        }
    }

    #pragma unroll
    for (int mt = 0; mt < 4; mt++) {
        #pragma unroll
        for (int nt = 0; nt < 4; nt++) {
            int row = m0 + wm + mt*16 + (lane >> 2);
            int col = n0 + wn + nt*8 + (lane & 3) * 2;
            #pragma unroll
            for (int half = 0; half < 2; half++) {
                int r = row + half * 8;
                float v0 = acc[mt][nt][half*2 + 0];
                float v1 = acc[mt][nt][half*2 + 1];
                if (col < Nglob) {
                    size_t o = (size_t)r * Nglob + col;
                    if (SILU) {
                        v0 = v0 / (1.0f + __expf(-v0));
                        v1 = v1 / (1.0f + __expf(-v1));
                        Cout[o]   = tf32_round(v0);
                        Cout[o+1] = tf32_round(v1);
                    } else {
                        Cout[o]   = v0;
                        Cout[o+1] = v1;
                    }
                }
            }
        }
    }
}

// ---- stage 5: ALL output families in ONE launch ----
// 832 blocks: [0,128) o0 | [128,320) o1 | [320,512) o1e | [512,832) o2.
// 256 thr, 128-row tile, BK=32, reg-prefetch + double-buffered smem, 1 barrier/chunk.
constexpr int kSkRowStride = 144;
constexpr int kSkASize     = 128 * kSkRowStride;    // 18432
constexpr int kSkBSize     = 32  * kSkRowStride;    // 4608 (OC max 32)
constexpr int kSkBuf       = kSkASize + kSkBSize;   // 23040

__global__ __launch_bounds__(256)
void skinny_all(const float* __restrict__ g,
                const float* __restrict__ w0,  const float* __restrict__ w1o,
                const float* __restrict__ w1e, const float* __restrict__ w2e,
                float* __restrict__ out)
{
    __shared__ char smem[2 * kSkBuf];
    const int tid  = threadIdx.x;
    const int wid  = tid >> 5, lane = tid & 31;
    const int b    = blockIdx.x;

    // ---- family decode ----
    const float* A; const float* Wp;
    int K, gOff, ldw, colOff = 0, outBase, outStride, comp = 0, OC, rb;
    if (b < 128) {
        rb = b & 63; colOff = (b >> 6) * 32;
        A = d_f0t; K = kM0; gOff = 0; Wp = w0; ldw = 64;
        outBase = 0; outStride = 1; OC = 32;
    } else if (b < 320) {
        int t = b - 128; comp = t >> 6; rb = t & 63;
        A = d_f1[comp]; K = kM1; gOff = kM0; Wp = w1o; ldw = 32;
        outBase = 64; outStride = 3; OC = 32;
    } else if (b < 512) {
        int t = b - 320; comp = t >> 6; rb = t & 63;
        A = d_f1e[comp]; K = kA1; gOff = kM0 + kM1; Wp = w1e; ldw = 16;
        outBase = 160; outStride = 3; OC = 16;
    } else {
        int t = b - 512; comp = t >> 6; rb = t & 63;
        A = d_f2[comp]; K = kP1; gOff = kM0 + kM1 + kA1; Wp = w2e; ldw = 16;
        outBase = 208; outStride = 5; OC = 16;
    }
    const int n0 = rb * 128;
    const int wm = wid * 16;              // 8 warps x 16 rows
    const int ocDiv8  = OC >> 3;
    const int ocDiv16 = OC >> 4;

    float acc[4][4];
    #pragma unroll
    for (int j = 0; j < 4; j++)
        #pragma unroll
        for (int q = 0; q < 4; q++) acc[j][q] = 0.0f;

    const int nChunks = (K + 31) / 32;

    float4 aP[4], gP[4];
    float  wP[4];

    auto load_regs = [&](int c) {
        const int k0 = c * 32;
        #pragma unroll
        for (int j = 0; j < 4; j++) {
            int i  = j * 256 + tid;
            int r  = i >> 3;
            int kq = i & 7;
            int gk = k0 + kq * 4;
            if (gk < K) {     // K % 4 == 0 always
                aP[j] = *reinterpret_cast<const float4*>(A + (size_t)(n0 + r)*K + gk);
                gP[j] = *reinterpret_cast<const float4*>(g + (size_t)(n0 + r)*kG + gOff + gk);
            } else {
                aP[j] = make_float4(0.f, 0.f, 0.f, 0.f);
                gP[j] = make_float4(1.f, 1.f, 1.f, 1.f);
            }
        }
        #pragma unroll
        for (int j = 0; j < 4; j++) {
            int i = j * 256 + tid;
            wP[j] = 0.f;
            if (i < OC * 32) {
                int k = i / OC, o = i % OC;
                if (k0 + k < K)
                    wP[j] = Wp[(size_t)(k0 + k)*ldw + colOff + o];
            }
        }
    };

    auto store_smem = [&](int buf) {
        char* base = smem + buf * kSkBuf;
        #pragma unroll
        for (int j = 0; j < 4; j++) {
            int i  = j * 256 + tid;
            int r  = i >> 3;
            int kq = i & 7;
            float4 a4;
            a4.x = tf32_round(aP[j].x * gP[j].x);
            a4.y = tf32_round(aP[j].y * gP[j].y);
            a4.z = tf32_round(aP[j].z * gP[j].z);
            a4.w = tf32_round(aP[j].w * gP[j].w);
            *reinterpret_cast<float4*>(base + r*kSkRowStride + kq*16) = a4;
        }
        #pragma unroll
        for (int j = 0; j < 4; j++) {
            int i = j * 256 + tid;
            if (i < OC * 32) {
                int k = i / OC, o = i % OC;
                *reinterpret_cast<float*>(base + kSkASize + o*kSkRowStride + k*4) = wP[j];
            }
        }
    };

    load_regs(0);

    for (int c = 0; c < nChunks; c++) {
        const int buf = c & 1;
        store_smem(buf);
        __syncthreads();
        if (c + 1 < nChunks) load_regs(c + 1);

        const uint32_t aT = smem_u32(smem) + buf * kSkBuf;
        const uint32_t bT = aT + kSkASize;

        #pragma unroll
        for (int s = 0; s < 4; s++) {
            uint32_t af[4], bf[4][2];
            const int arow = wm + (lane & 15);
            const int acol = s * 32 + (lane >> 4) * 16;
            ldm_x4(af, aT + (uint32_t)arow * kSkRowStride + acol);
            const int bg  = lane >> 3;
            const int br  = lane & 7;
            const int bnt = bg >> 1;
            const int bkh = (bg & 1) * 16;
            #pragma unroll
            for (int np = 0; np < 2; np++) {
                if (np < ocDiv16) {
                    uint32_t off = (uint32_t)((np*2 + bnt)*8 + br) * kSkRowStride
                                 + s*32 + bkh;
                    ldm_x4(&bf[np*2][0], bT + off);
                }
            }
            #pragma unroll
            for (int nt = 0; nt < 4; nt++)
                if (nt < ocDiv8)
                    mma_tf32(acc[nt], af, bf[nt]);
        }
    }

    // epilogue: strided column placement into out[N, 288]
    #pragma unroll
    for (int nt = 0; nt < 4; nt++) {
        if (nt < ocDiv8) {
            int row = n0 + wm + (lane >> 2);
            int oc  = colOff + nt*8 + (lane & 3) * 2;
            #pragma unroll
            for (int half = 0; half < 2; half++) {
                int r = row + half * 8;
                size_t o = (size_t)r * kOUTW + outBase + comp + (size_t)oc * outStride;
                out[o]             = acc[nt][half*2 + 0];
                out[o + outStride] = acc[nt][half*2 + 1];
            }
        }
    }
}

// ---------------- launch ----------------
extern "C" void kernel_launch(void* const* d_in, const int* in_sizes, int n_in,
                              void* d_out, int out_size)
{
    const float* xs  = (const float*)d_in[0];
    const float* xv  = (const float*)d_in[1];
    const float* w1  = (const float*)d_in[2];
    const float* w2  = (const float*)d_in[3];
    const float* w0  = (const float*)d_in[4];
    const float* w1o = (const float*)d_in[5];
    const float* w1e = (const float*)d_in[6];
    const float* w2e = (const float*)d_in[7];
    float* out = (float*)d_out;

    void *pf0t, *ph, *pg, *pw1t, *pw2t;
    cudaGetSymbolAddress(&pf0t, d_f0t);
    cudaGetSymbolAddress(&ph,   d_h);
    cudaGetSymbolAddress(&pg,   d_g);
    cudaGetSymbolAddress(&pw1t, d_w1t);
    cudaGetSymbolAddress(&pw2t, d_w2t);

    float* f0tv = (float*)pf0t;
    float* hv   = (float*)ph;
    float* gv   = (float*)pg;
    float* w1tv = (float*)pw1t;
    float* w2tv = (float*)pw2t;

    cudaFuncSetAttribute(mma_gemm<true>,  cudaFuncAttributeMaxDynamicSharedMemorySize, kGemmSmem);
    cudaFuncSetAttribute(mma_gemm<false>, cudaFuncAttributeMaxDynamicSharedMemorySize, kGemmSmem);

    // stage 0: weight transpose + tf32 rounding
    prep_weight<<<dim3((kM0+31)/32, (kM0+31)/32), 256>>>(w1, w1tv, kM0, kM0);
    prep_weight<<<dim3((kG +31)/32, (kM0+31)/32), 256>>>(w2, w2tv, kM0, kG);

    // stage 1: features
    build_features<<<kN, 256>>>(xs, xv);

    // stage 2: h = tf32(silu(f0t @ W1))      [8192 x 2672]
    {
        dim3 grid((kM0 + 127)/128, kN/128);
        mma_gemm<true><<<grid, 256, kGemmSmem>>>(f0tv, w1tv, hv, kM0, kM0);
    }
    // stage 3: g = h @ W2 (fp32)             [8192 x 5776]
    {
        dim3 grid((kG + 127)/128, kN/128);
        mma_gemm<false><<<grid, 256, kGemmSmem>>>(hv, w2tv, gv, kM0, kG);
    }

    // stage 5: all gated output GEMMs in one launch
    skinny_all<<<832, 256>>>(gv, w0, w1o, w1e, w2e, out);
}